// round 6
// baseline (speedup 1.0000x reference)
#include <cuda_runtime.h>
#include <cuda_bf16.h>
#include <stdint.h>
#include <math.h>

#define S_LEN   2048
#define D_MODEL 1024
#define NHEAD   16
#define HDIM    64

typedef __nv_bfloat16 bf16;

// ---------------------------------------------------------------------------
// Device-global scratch (allocation-free, zero-init at load).
// ---------------------------------------------------------------------------
static __device__ bf16  g_iqh[S_LEN * D_MODEL], g_iql[S_LEN * D_MODEL];
static __device__ bf16  g_ikh[S_LEN * D_MODEL], g_ikl[S_LEN * D_MODEL];
static __device__ bf16  g_ivh[S_LEN * D_MODEL], g_ivl[S_LEN * D_MODEL];
static __device__ bf16  g_wqh[D_MODEL * D_MODEL], g_wql[D_MODEL * D_MODEL];
static __device__ bf16  g_wkh[D_MODEL * D_MODEL], g_wkl[D_MODEL * D_MODEL];
static __device__ bf16  g_wvh[D_MODEL * D_MODEL], g_wvl[D_MODEL * D_MODEL];
static __device__ bf16  g_woh[D_MODEL * D_MODEL], g_wol[D_MODEL * D_MODEL];
static __device__ bf16  g_qh[S_LEN * D_MODEL], g_ql[S_LEN * D_MODEL];   // pre-scaled by 0.125
static __device__ bf16  g_kh[S_LEN * D_MODEL], g_kl[S_LEN * D_MODEL];
static __device__ bf16  g_vth[D_MODEL * S_LEN], g_vtl[D_MODEL * S_LEN]; // [h*64+v][t]
static __device__ bf16  g_zh[S_LEN * D_MODEL], g_zl[S_LEN * D_MODEL];
static __device__ float g_part[NHEAD * 16 * S_LEN];   // [h][sblock][t] partial exp sums
static __device__ float g_L[NHEAD * S_LEN];
static __device__ float g_c[NHEAD * HDIM];
static __device__ float g_badj[D_MODEL];

// ---------------------------------------------------------------------------
// PTX helpers (generic sm_80-class PTX, legal under compute_103)
// ---------------------------------------------------------------------------
__device__ __forceinline__ uint32_t smem_u32(const void* p) {
    uint32_t a;
    asm("{ .reg .u64 t; cvta.to.shared.u64 t, %1; cvt.u32.u64 %0, t; }" : "=r"(a) : "l"(p));
    return a;
}
__device__ __forceinline__ void cp_async16(uint32_t dst, const void* src) {
    asm volatile("cp.async.cg.shared.global [%0], [%1], 16;" :: "r"(dst), "l"(src));
}
__device__ __forceinline__ void cp_commit() {
    asm volatile("cp.async.commit_group;" ::: "memory");
}
template<int N> __device__ __forceinline__ void cp_wait() {
    asm volatile("cp.async.wait_group %0;" :: "n"(N) : "memory");
}

#define LDSM_X4(r, addr) \
    asm volatile("ldmatrix.sync.aligned.m8n8.x4.shared.b16 {%0,%1,%2,%3}, [%4];" \
        : "=r"((r)[0]), "=r"((r)[1]), "=r"((r)[2]), "=r"((r)[3]) : "r"(addr))

__device__ __forceinline__ void mma16816(float* c, const uint32_t* a, const uint32_t* b) {
    asm volatile(
        "mma.sync.aligned.m16n8k16.row.col.f32.bf16.bf16.f32 "
        "{%0,%1,%2,%3}, {%4,%5,%6,%7}, {%8,%9}, {%0,%1,%2,%3};"
        : "+f"(c[0]), "+f"(c[1]), "+f"(c[2]), "+f"(c[3])
        : "r"(a[0]), "r"(a[1]), "r"(a[2]), "r"(a[3]), "r"(b[0]), "r"(b[1]));
}

// hi/lo bf16 split of a float pair using packed cvt (2 cvts instead of 4)
__device__ __forceinline__ uint32_t split2(float v0, float v1, uint32_t& lopack) {
    uint32_t hp;
    asm("cvt.rn.bf16x2.f32 %0, %1, %2;" : "=r"(hp) : "f"(v1), "f"(v0));
    float h0 = __uint_as_float(hp << 16);
    float h1 = __uint_as_float(hp & 0xffff0000u);
    asm("cvt.rn.bf16x2.f32 %0, %1, %2;" : "=r"(lopack) : "f"(v1 - h1), "f"(v0 - h0));
    return hp;
}

// exp on the FMA pipe (no MUFU): exp(x) = 2^(x*log2e), deg-5 on 2^f
__device__ __forceinline__ float exp_poly(float x) {
    float y  = x * 1.4426950408889634f;
    float fy = y + 12582912.0f;                 // round to nearest int
    float n  = fy - 12582912.0f;
    float f  = y - n;                           // [-0.5, 0.5]
    float p = fmaf(0.00133336f, f, 0.00961813f);
    p = fmaf(p, f, 0.05550411f);
    p = fmaf(p, f, 0.24022651f);
    p = fmaf(p, f, 0.69314718f);
    p = fmaf(p, f, 1.0f);
    return __int_as_float(__float_as_int(p) + (__float_as_int(fy) << 23));
}

// ---------------------------------------------------------------------------
// Projection GEMM machinery: 128x128 tile, BK=32, 3-stage cp.async pipeline.
// 3-pass split-bf16: acc += Ahi*Bhi + Ahi*Blo + Alo*Bhi, fp32 accumulators.
// ---------------------------------------------------------------------------
#define PITCHB 80

__device__ __forceinline__ void mma_mainloop128(
    uint32_t sb, float (&acc)[2][8][4],
    const bf16* __restrict__ Ahi, const bf16* __restrict__ Alo, int lda, int arow0,
    const bf16* __restrict__ Bhi, const bf16* __restrict__ Blo, int ldb, int brow0,
    int nchunks)
{
    constexpr int AB = 128 * PITCHB;
    constexpr int BB = 128 * PITCHB;
    constexpr int STAGE = 2 * AB + 2 * BB;        // 40960
    const int tid = threadIdx.x, lane = tid & 31, wid = tid >> 5;
    const int wm = (wid & 3) * 32, wn = (wid >> 2) * 64;

    auto load = [&](int c) {
        uint32_t s = sb + (uint32_t)(c % 3) * STAGE;
        const int k0 = c * 32;
        for (int i = tid; i < 128 * 4; i += 256) {
            int r = i >> 2, cb = (i & 3) << 4;
            uint32_t d = s + (uint32_t)(r * PITCHB + cb);
            cp_async16(d,      (const char*)(Ahi + (size_t)(arow0 + r) * lda + k0) + cb);
            cp_async16(d + AB, (const char*)(Alo + (size_t)(arow0 + r) * lda + k0) + cb);
        }
        for (int i = tid; i < 128 * 4; i += 256) {
            int r = i >> 2, cb = (i & 3) << 4;
            uint32_t d = s + 2 * AB + (uint32_t)(r * PITCHB + cb);
            cp_async16(d,      (const char*)(Bhi + (size_t)(brow0 + r) * ldb + k0) + cb);
            cp_async16(d + BB, (const char*)(Blo + (size_t)(brow0 + r) * ldb + k0) + cb);
        }
        cp_commit();
    };

    const uint32_t aoff = (uint32_t)((wm + (lane & 15)) * PITCHB + ((lane & 16) ? 16 : 0));
    const uint32_t boff = (uint32_t)((wn + (lane & 7) + ((lane & 16) ? 8 : 0)) * PITCHB +
                                     ((lane & 8) ? 16 : 0));

    load(0);
    if (nchunks > 1) load(1);
    for (int c = 0; c < nchunks; c++) {
        if (c + 2 < nchunks) { load(c + 2); cp_wait<2>(); }
        else if (c + 1 < nchunks) cp_wait<1>();
        else cp_wait<0>();
        __syncthreads();
        uint32_t s  = sb + (uint32_t)(c % 3) * STAGE;
        uint32_t sa = s + aoff;
        uint32_t sbb = s + 2 * AB + boff;
#pragma unroll
        for (int ks = 0; ks < 2; ks++) {
            const uint32_t ko = (uint32_t)(ks * 32);
            uint32_t ah[2][4], al[2][4];
            LDSM_X4(ah[0], sa + ko);
            LDSM_X4(ah[1], sa + 16 * PITCHB + ko);
            LDSM_X4(al[0], sa + AB + ko);
            LDSM_X4(al[1], sa + AB + 16 * PITCHB + ko);
            uint32_t bh[8][2], bl[8][2];
#pragma unroll
            for (int p = 0; p < 4; p++) {
                uint32_t r4[4];
                LDSM_X4(r4, sbb + (uint32_t)(p * 16 * PITCHB) + ko);
                bh[2*p][0] = r4[0]; bh[2*p][1] = r4[1];
                bh[2*p+1][0] = r4[2]; bh[2*p+1][1] = r4[3];
                LDSM_X4(r4, sbb + BB + (uint32_t)(p * 16 * PITCHB) + ko);
                bl[2*p][0] = r4[0]; bl[2*p][1] = r4[1];
                bl[2*p+1][0] = r4[2]; bl[2*p+1][1] = r4[3];
            }
#pragma unroll
            for (int f = 0; f < 2; f++)
#pragma unroll
                for (int j = 0; j < 8; j++)
                    mma16816(acc[f][j], ah[f], bh[j]);
#pragma unroll
            for (int f = 0; f < 2; f++)
#pragma unroll
                for (int j = 0; j < 8; j++)
                    mma16816(acc[f][j], ah[f], bl[j]);
#pragma unroll
            for (int f = 0; f < 2; f++)
#pragma unroll
                for (int j = 0; j < 8; j++)
                    mma16816(acc[f][j], al[f], bh[j]);
        }
        __syncthreads();
    }
}

#define SMEM_PROJ (3 * (2 * 128 * PITCHB + 2 * 128 * PITCHB))   // 122880

// ---------------------------------------------------------------------------
// Projection GEMM: C[2048,1024] = (A*B^T + bias) * scale.
// MODE 0: bf16 hi/lo row-major   MODE 1: hi/lo transposed [col][row]
// MODE 2: fp32 row-major
// ---------------------------------------------------------------------------
template<int MODE>
__global__ __launch_bounds__(256) void gemm_proj(
    const bf16* __restrict__ Ahi, const bf16* __restrict__ Alo,
    const bf16* __restrict__ Bhi, const bf16* __restrict__ Blo,
    const float* __restrict__ bias, float scale,
    bf16* __restrict__ ohi, bf16* __restrict__ olo, float* __restrict__ ofp)
{
    extern __shared__ char smem[];
    uint32_t sb = smem_u32(smem);
    const int row0 = blockIdx.y << 7, col0 = blockIdx.x << 7;
    float acc[2][8][4];
#pragma unroll
    for (int f = 0; f < 2; f++)
#pragma unroll
        for (int j = 0; j < 8; j++)
#pragma unroll
            for (int q = 0; q < 4; q++) acc[f][j][q] = 0.f;

    mma_mainloop128(sb, acc, Ahi, Alo, D_MODEL, row0, Bhi, Blo, D_MODEL, col0, D_MODEL / 32);

    const int lane = threadIdx.x & 31, wid = threadIdx.x >> 5;
    const int wm = (wid & 3) * 32, wn = (wid >> 2) * 64;
    const int rb = row0 + wm + (lane >> 2);
    const int cb = col0 + wn + (lane & 3) * 2;
#pragma unroll
    for (int f = 0; f < 2; f++)
#pragma unroll
        for (int j = 0; j < 8; j++)
#pragma unroll
            for (int rh = 0; rh < 2; rh++) {
                const int r = rb + f * 16 + rh * 8;
                const int col = cb + j * 8;
                float v0 = (acc[f][j][rh * 2 + 0] + bias[col])     * scale;
                float v1 = (acc[f][j][rh * 2 + 1] + bias[col + 1]) * scale;
                if (MODE == 2) {
                    *(float2*)(ofp + (size_t)r * D_MODEL + col) = make_float2(v0, v1);
                } else if (MODE == 1) {
                    uint32_t lp, hp = split2(v0, v1, lp);
                    ohi[(size_t)col * S_LEN + r]       = __ushort_as_bfloat16((unsigned short)hp);
                    ohi[(size_t)(col + 1) * S_LEN + r] = __ushort_as_bfloat16((unsigned short)(hp >> 16));
                    olo[(size_t)col * S_LEN + r]       = __ushort_as_bfloat16((unsigned short)lp);
                    olo[(size_t)(col + 1) * S_LEN + r] = __ushort_as_bfloat16((unsigned short)(lp >> 16));
                } else {
                    uint32_t lp, hp = split2(v0, v1, lp);
                    *(uint32_t*)(ohi + (size_t)r * D_MODEL + col) = hp;
                    *(uint32_t*)(olo + (size_t)r * D_MODEL + col) = lp;
                }
            }
}

// ---------------------------------------------------------------------------
// Fused attention. Q pre-scaled by 0.125 -> S is already qk/8.
// Diagonal tiles: per-warp bounds skip fully-masked fragments.
// ---------------------------------------------------------------------------
#define PQB  144
#define PVB  272
#define QSZ  (128 * PQB)
#define KSTG (2 * QSZ)
#define VSZ  (64 * PVB)
#define VSTG (2 * VSZ)
#define OFF_K   (2 * QSZ)
#define OFF_V   (OFF_K + 2 * KSTG)
#define OFF_PART (OFF_V + 2 * VSTG)
#define FATTN_SMEM (OFF_PART + 8 * 128 * 4)

__global__ __launch_bounds__(256) void fused_attn()
{
    extern __shared__ char smem[];
    uint32_t sb = smem_u32(smem);
    const int h = blockIdx.y;
    const int tid = threadIdx.x, lane = tid & 31, wid = tid >> 5;
    float* spart = (float*)(smem + OFF_PART);

    const uint32_t qoff = sb + (uint32_t)((wid * 16 + (lane & 15)) * PQB + ((lane & 16) ? 16 : 0));
    const uint32_t kvlane = (uint32_t)((lane & 7) + ((lane & 16) ? 8 : 0));
    const uint32_t koff_l = kvlane * PQB + ((lane & 8) ? 16 : 0);
    const uint32_t voff_l = kvlane * PVB + ((lane & 8) ? 16 : 0);

    for (int half = 0; half < 2; half++) {
        const int sblk = half ? (15 - (int)blockIdx.x) : (int)blockIdx.x;
        const int row0 = sblk << 7;
        const int ntb  = sblk + 1;

        for (int i = tid; i < 128 * 8; i += 256) {
            int r = i >> 3, cbyte = (i & 7) << 4;
            cp_async16(sb + (uint32_t)(r * PQB) + cbyte,
                       (const char*)(g_qh + (size_t)(row0 + r) * D_MODEL + h * HDIM) + cbyte);
            cp_async16(sb + QSZ + (uint32_t)(r * PQB) + cbyte,
                       (const char*)(g_ql + (size_t)(row0 + r) * D_MODEL + h * HDIM) + cbyte);
        }
        cp_commit();

        auto loadKV = [&](int tb) {
            uint32_t kbase = sb + OFF_K + (uint32_t)(tb & 1) * KSTG;
            uint32_t vbase = sb + OFF_V + (uint32_t)(tb & 1) * VSTG;
            const int col0 = tb << 7;
            for (int i = tid; i < 128 * 8; i += 256) {
                int r = i >> 3, cbyte = (i & 7) << 4;
                cp_async16(kbase + (uint32_t)(r * PQB) + cbyte,
                           (const char*)(g_kh + (size_t)(col0 + r) * D_MODEL + h * HDIM) + cbyte);
                cp_async16(kbase + QSZ + (uint32_t)(r * PQB) + cbyte,
                           (const char*)(g_kl + (size_t)(col0 + r) * D_MODEL + h * HDIM) + cbyte);
            }
            for (int i = tid; i < 64 * 16; i += 256) {
                int r = i >> 4, cbyte = (i & 15) << 4;
                cp_async16(vbase + (uint32_t)(r * PVB) + cbyte,
                           (const char*)(g_vth + (size_t)(h * HDIM + r) * S_LEN + col0) + cbyte);
                cp_async16(vbase + VSZ + (uint32_t)(r * PVB) + cbyte,
                           (const char*)(g_vtl + (size_t)(h * HDIM + r) * S_LEN + col0) + cbyte);
            }
            cp_commit();
        };
        loadKV(0);

        float oacc[8][4];
#pragma unroll
        for (int j = 0; j < 8; j++)
#pragma unroll
            for (int q = 0; q < 4; q++) oacc[j][q] = 0.f;

        for (int tb = 0; tb < ntb; tb++) {
            if (tb + 1 < ntb) { loadKV(tb + 1); cp_wait<1>(); }
            else              { cp_wait<0>(); }
            __syncthreads();

            uint32_t kbase = sb + OFF_K + (uint32_t)(tb & 1) * KSTG;
            uint32_t vbase = sb + OFF_V + (uint32_t)(tb & 1) * VSTG;

            const bool diag = (tb == sblk);
            const int pmax  = diag ? (wid + 1) : 8;      // 16-col groups needed
            const int nfmax = diag ? (2 * wid + 2) : 16; // 8-col fragments needed

            // ---- MMA1: S[16 x 128] per warp (cols beyond pmax stay 0) ----
            float sacc[16][4];
#pragma unroll
            for (int j = 0; j < 16; j++)
#pragma unroll
                for (int q = 0; q < 4; q++) sacc[j][q] = 0.f;

            const uint32_t koff = kbase + koff_l;
#pragma unroll
            for (int ks = 0; ks < 4; ks++) {
                const uint32_t ko = (uint32_t)(ks * 32);
                uint32_t ah[4], al[4];
                LDSM_X4(ah, qoff + ko);
                LDSM_X4(al, qoff + QSZ + ko);
#pragma unroll
                for (int p = 0; p < 8; p++) {
                    if (p < pmax) {
                        uint32_t bh[4], bl[4];
                        LDSM_X4(bh, koff + (uint32_t)(p * 16 * PQB) + ko);
                        LDSM_X4(bl, koff + QSZ + (uint32_t)(p * 16 * PQB) + ko);
                        mma16816(sacc[2*p],   ah, bh);
                        mma16816(sacc[2*p+1], ah, bh + 2);
                        mma16816(sacc[2*p],   ah, bl);
                        mma16816(sacc[2*p+1], ah, bl + 2);
                        mma16816(sacc[2*p],   al, bh);
                        mma16816(sacc[2*p+1], al, bh + 2);
                    }
                }
            }

            // ---- mask + exp partial column sums (5:11 MUFU:poly split) ----
            const int r0 = row0 + wid * 16 + (lane >> 2);
            const int r1 = r0 + 8;
            const int cb2 = (tb << 7) + 2 * (lane & 3);
#pragma unroll
            for (int nf = 0; nf < 16; nf++) {
                float eA = 0.f, eB = 0.f;
                if (nf < nfmax) {
                    const int c0 = cb2 + nf * 8;
                    float s0 = sacc[nf][0], s1 = sacc[nf][1];
                    float s2 = sacc[nf][2], s3 = sacc[nf][3];
                    bool m0 = true, m1 = true, m2 = true, m3 = true;
                    if (diag) {
                        m0 = (c0 <= r0); m1 = (c0 + 1 <= r0);
                        m2 = (c0 <= r1); m3 = (c0 + 1 <= r1);
                        s0 = m0 ? s0 : 0.f; s1 = m1 ? s1 : 0.f;
                        s2 = m2 ? s2 : 0.f; s3 = m3 ? s3 : 0.f;
                        sacc[nf][0] = s0; sacc[nf][1] = s1;
                        sacc[nf][2] = s2; sacc[nf][3] = s3;
                    }
                    float e0, e1, e2, e3;
                    if (nf < 5) {           // MUFU share ~0.31
                        e0 = __expf(s0); e1 = __expf(s1);
                        e2 = __expf(s2); e3 = __expf(s3);
                    } else {                // FMA-pipe poly share ~0.69
                        e0 = exp_poly(s0); e1 = exp_poly(s1);
                        e2 = exp_poly(s2); e3 = exp_poly(s3);
                    }
                    if (diag) {
                        e0 = m0 ? e0 : 0.f; e1 = m1 ? e1 : 0.f;
                        e2 = m2 ? e2 : 0.f; e3 = m3 ? e3 : 0.f;
                    }
                    eA = e0 + e2; eB = e1 + e3;
                    eA += __shfl_xor_sync(0xffffffffu, eA, 4);
                    eA += __shfl_xor_sync(0xffffffffu, eA, 8);
                    eA += __shfl_xor_sync(0xffffffffu, eA, 16);
                    eB += __shfl_xor_sync(0xffffffffu, eB, 4);
                    eB += __shfl_xor_sync(0xffffffffu, eB, 8);
                    eB += __shfl_xor_sync(0xffffffffu, eB, 16);
                }
                if (lane < 4) {
                    spart[wid * 128 + nf * 8 + 2 * lane]     = eA;
                    spart[wid * 128 + nf * 8 + 2 * lane + 1] = eB;
                }
            }

            // ---- MMA2: O += S @ V^T (kc beyond pmax is all-zero S) ----
            const uint32_t voff = vbase + voff_l;
#pragma unroll
            for (int kc = 0; kc < 8; kc++) {
                if (kc < pmax) {
                    uint32_t ahi[4], alo[4];
                    ahi[0] = split2(sacc[2*kc][0],   sacc[2*kc][1],   alo[0]);
                    ahi[1] = split2(sacc[2*kc][2],   sacc[2*kc][3],   alo[1]);
                    ahi[2] = split2(sacc[2*kc+1][0], sacc[2*kc+1][1], alo[2]);
                    ahi[3] = split2(sacc[2*kc+1][2], sacc[2*kc+1][3], alo[3]);
                    const uint32_t ko = (uint32_t)(kc * 32);
#pragma unroll
                    for (int p = 0; p < 4; p++) {
                        uint32_t bh[4], bl[4];
                        LDSM_X4(bh, voff + (uint32_t)(p * 16 * PVB) + ko);
                        LDSM_X4(bl, voff + VSZ + (uint32_t)(p * 16 * PVB) + ko);
                        mma16816(oacc[2*p],   ahi, bh);
                        mma16816(oacc[2*p+1], ahi, bh + 2);
                        mma16816(oacc[2*p],   ahi, bl);
                        mma16816(oacc[2*p+1], ahi, bl + 2);
                        mma16816(oacc[2*p],   alo, bh);
                        mma16816(oacc[2*p+1], alo, bh + 2);
                    }
                }
            }

            __syncthreads();
            if (tid < 128) {
                float s = 0.f;
#pragma unroll
                for (int w = 0; w < 8; w++) s += spart[w * 128 + tid];
                g_part[((h * 16 + sblk) << 11) + (tb << 7) + tid] = s;
            }
        }

        // ---- epilogue: Z = O (Q pre-scaled; -c folded into out-proj bias) ----
        {
            const int r0 = row0 + wid * 16 + (lane >> 2);
            const int cb2 = 2 * (lane & 3);
#pragma unroll
            for (int nf = 0; nf < 8; nf++) {
                const int col = h * HDIM + nf * 8 + cb2;
                uint32_t lp, hp;
                hp = split2(oacc[nf][0], oacc[nf][1], lp);
                *(uint32_t*)(g_zh + (size_t)r0 * D_MODEL + col) = hp;
                *(uint32_t*)(g_zl + (size_t)r0 * D_MODEL + col) = lp;
                hp = split2(oacc[nf][2], oacc[nf][3], lp);
                *(uint32_t*)(g_zh + (size_t)(r0 + 8) * D_MODEL + col) = hp;
                *(uint32_t*)(g_zl + (size_t)(r0 + 8) * D_MODEL + col) = lp;
            }
        }
        __syncthreads();
    }
}

// ---------------------------------------------------------------------------
// L[h][t] = log( t + sum_{sb>=tb} part[h][sb][t] )
// ---------------------------------------------------------------------------
__global__ __launch_bounds__(128) void lse_reduce()
{
    const int h = blockIdx.y, tb = blockIdx.x;
    const int t = (tb << 7) + threadIdx.x;
    float acc = (float)t;
    for (int sbk = tb; sbk < 16; sbk++)
        acc += g_part[((h * 16 + sbk) << 11) + t];
    g_L[h * S_LEN + t] = logf(acc);
}

// ---------------------------------------------------------------------------
// c[h][v] = sum_t L[h][t] * V[t][h*64+v]
// ---------------------------------------------------------------------------
__global__ __launch_bounds__(256) void compute_c_tc()
{
    __shared__ float part[4][HDIM];
    const int h = blockIdx.x;
    const int v = threadIdx.x & 63;
    const int g = threadIdx.x >> 6;
    const bf16* th = g_vth + (size_t)(h * HDIM + v) * S_LEN;
    const bf16* tl = g_vtl + (size_t)(h * HDIM + v) * S_LEN;
    const float* Lh = g_L + h * S_LEN;
    float sum = 0.f;
    const int t0 = g * (S_LEN / 4);
    for (int t = t0; t < t0 + S_LEN / 4; t++)
        sum = fmaf(Lh[t], __bfloat162float(th[t]) + __bfloat162float(tl[t]), sum);
    part[g][v] = sum;
    __syncthreads();
    if (g == 0)
        g_c[h * HDIM + v] = (part[0][v] + part[1][v]) + (part[2][v] + part[3][v]);
}

// ---------------------------------------------------------------------------
// b'[i] = WOb[i] - sum_j WOw[i][j] * c[j]
// ---------------------------------------------------------------------------
__global__ __launch_bounds__(256) void bias_adjust(
    const float* __restrict__ WOw, const float* __restrict__ WOb)
{
    const int lane = threadIdx.x & 31, wid = threadIdx.x >> 5;
    for (int rr = 0; rr < 4; rr++) {
        const int row = (blockIdx.x * 8 + wid) * 4 + rr;
        const float* wr = WOw + (size_t)row * D_MODEL;
        float s = 0.f;
        for (int j = lane; j < D_MODEL; j += 32)
            s = fmaf(wr[j], g_c[j], s);
#pragma unroll
        for (int o = 16; o > 0; o >>= 1) s += __shfl_xor_sync(0xffffffffu, s, o);
        if (lane == 0) g_badj[row] = WOb[row] - s;
    }
}

// ---------------------------------------------------------------------------
// fp32 -> bf16 hi/lo split, 8 floats (4 pairs) per thread
// ---------------------------------------------------------------------------
__global__ __launch_bounds__(256) void split_kernel(
    const float4* __restrict__ src, uint4* __restrict__ hi, uint4* __restrict__ lo)
{
    const int i = blockIdx.x * 256 + threadIdx.x;
    float4 a = src[2 * i], b = src[2 * i + 1];
    uint4 h, l;
    h.x = split2(a.x, a.y, l.x);
    h.y = split2(a.z, a.w, l.y);
    h.z = split2(b.x, b.y, l.z);
    h.w = split2(b.z, b.w, l.w);
    hi[i] = h;
    lo[i] = l;
}

// ---------------------------------------------------------------------------
extern "C" void kernel_launch(void* const* d_in, const int* in_sizes, int n_in,
                              void* d_out, int out_size)
{
    const float* Qin = (const float*)d_in[0];
    const float* Kin = (const float*)d_in[1];
    const float* Vin = (const float*)d_in[2];
    const float* WQw = (const float*)d_in[3];
    const float* WQb = (const float*)d_in[4];
    const float* WKw = (const float*)d_in[5];
    const float* WKb = (const float*)d_in[6];
    const float* WVw = (const float*)d_in[7];
    const float* WVb = (const float*)d_in[8];
    const float* WOw = (const float*)d_in[9];
    const float* WOb = (const float*)d_in[10];
    float* Out = (float*)d_out;

#define GETP(name, sym) void* name; cudaGetSymbolAddress(&name, sym)
    GETP(iqh, g_iqh); GETP(iql, g_iql); GETP(ikh, g_ikh); GETP(ikl, g_ikl);
    GETP(ivh, g_ivh); GETP(ivl, g_ivl);
    GETP(wqh, g_wqh); GETP(wql, g_wql); GETP(wkh, g_wkh); GETP(wkl, g_wkl);
    GETP(wvh, g_wvh); GETP(wvl, g_wvl); GETP(woh, g_woh); GETP(wol, g_wol);
    GETP(qh, g_qh);   GETP(ql, g_ql);   GETP(kh, g_kh);   GETP(kl, g_kl);
    GETP(vth, g_vth); GETP(vtl, g_vtl);
    GETP(zh, g_zh);   GETP(zl, g_zl);
    GETP(badj, g_badj);
#undef GETP

    cudaFuncSetAttribute(gemm_proj<0>, cudaFuncAttributeMaxDynamicSharedMemorySize, SMEM_PROJ);
    cudaFuncSetAttribute(gemm_proj<1>, cudaFuncAttributeMaxDynamicSharedMemorySize, SMEM_PROJ);
    cudaFuncSetAttribute(gemm_proj<2>, cudaFuncAttributeMaxDynamicSharedMemorySize, SMEM_PROJ);
    cudaFuncSetAttribute(fused_attn,   cudaFuncAttributeMaxDynamicSharedMemorySize, FATTN_SMEM);

    const int nbIn = (S_LEN * D_MODEL) / (8 * 256);    // 1024 blocks
    const int nbW  = (D_MODEL * D_MODEL) / (8 * 256);  // 512 blocks
    dim3 blk(256);

    // 1) hi/lo splits (vectorized: 8 floats per thread)
    split_kernel<<<nbIn, blk>>>((const float4*)Qin, (uint4*)iqh, (uint4*)iql);
    split_kernel<<<nbIn, blk>>>((const float4*)Kin, (uint4*)ikh, (uint4*)ikl);
    split_kernel<<<nbIn, blk>>>((const float4*)Vin, (uint4*)ivh, (uint4*)ivl);
    split_kernel<<<nbW, blk>>>((const float4*)WQw, (uint4*)wqh, (uint4*)wql);
    split_kernel<<<nbW, blk>>>((const float4*)WKw, (uint4*)wkh, (uint4*)wkl);
    split_kernel<<<nbW, blk>>>((const float4*)WVw, (uint4*)wvh, (uint4*)wvl);
    split_kernel<<<nbW, blk>>>((const float4*)WOw, (uint4*)woh, (uint4*)wol);

    // 2) projections (Q pre-scaled by 0.125)
    dim3 gproj(D_MODEL / 128, S_LEN / 128);
    gemm_proj<0><<<gproj, blk, SMEM_PROJ>>>((bf16*)iqh, (bf16*)iql, (bf16*)wqh, (bf16*)wql,
                                            WQb, 0.125f, (bf16*)qh, (bf16*)ql, nullptr);
    gemm_proj<0><<<gproj, blk, SMEM_PROJ>>>((bf16*)ikh, (bf16*)ikl, (bf16*)wkh, (bf16*)wkl,
                                            WKb, 1.0f, (bf16*)kh, (bf16*)kl, nullptr);
    gemm_proj<1><<<gproj, blk, SMEM_PROJ>>>((bf16*)ivh, (bf16*)ivl, (bf16*)wvh, (bf16*)wvl,
                                            WVb, 1.0f, (bf16*)vth, (bf16*)vtl, nullptr);

    // 3) fused attention
    dim3 gfa(8, NHEAD);
    fused_attn<<<gfa, blk, FATTN_SMEM>>>();

    // 4) L, c, adjusted bias
    dim3 glse(16, NHEAD);
    lse_reduce<<<glse, dim3(128)>>>();
    compute_c_tc<<<NHEAD, blk>>>();
    bias_adjust<<<32, blk>>>(WOw, WOb);

    // 5) output projection with folded bias
    gemm_proj<2><<<gproj, blk, SMEM_PROJ>>>((bf16*)zh, (bf16*)zl, (bf16*)woh, (bf16*)wol,
                                            (const float*)badj, 1.0f, nullptr, nullptr, Out);
}

// round 7
// speedup vs baseline: 1.2707x; 1.2707x over previous
#include <cuda_runtime.h>
#include <cuda_fp16.h>
#include <stdint.h>
#include <math.h>

#define S_LEN   2048
#define D_MODEL 1024
#define NHEAD   16
#define HDIM    64

typedef __half fp16;

// ---------------------------------------------------------------------------
// Device-global scratch (allocation-free, zero-init at load).
// ---------------------------------------------------------------------------
static __device__ fp16  g_iq[S_LEN * D_MODEL], g_ik[S_LEN * D_MODEL], g_iv[S_LEN * D_MODEL]; // input hi
static __device__ fp16  g_wqh[D_MODEL * D_MODEL], g_wql[D_MODEL * D_MODEL];
static __device__ fp16  g_wkh[D_MODEL * D_MODEL], g_wkl[D_MODEL * D_MODEL];
static __device__ fp16  g_wvh[D_MODEL * D_MODEL], g_wvl[D_MODEL * D_MODEL];
static __device__ fp16  g_woh[D_MODEL * D_MODEL], g_wol[D_MODEL * D_MODEL];
static __device__ fp16  g_qh[S_LEN * D_MODEL], g_ql[S_LEN * D_MODEL];   // q hi/lo, pre-scaled 0.125
static __device__ fp16  g_kh[S_LEN * D_MODEL], g_kl[S_LEN * D_MODEL];
static __device__ fp16  g_vth[D_MODEL * S_LEN], g_vtl[D_MODEL * S_LEN]; // [h*64+v][t]
static __device__ fp16  g_zh[S_LEN * D_MODEL];                          // Z hi only
static __device__ float g_part[NHEAD * 16 * S_LEN];
static __device__ float g_L[NHEAD * S_LEN];
static __device__ float g_c[NHEAD * HDIM];
static __device__ float g_badj[D_MODEL];

// ---------------------------------------------------------------------------
// PTX helpers (generic sm_80-class PTX, legal under compute_103)
// ---------------------------------------------------------------------------
__device__ __forceinline__ uint32_t smem_u32(const void* p) {
    uint32_t a;
    asm("{ .reg .u64 t; cvta.to.shared.u64 t, %1; cvt.u32.u64 %0, t; }" : "=r"(a) : "l"(p));
    return a;
}
__device__ __forceinline__ void cp_async16(uint32_t dst, const void* src) {
    asm volatile("cp.async.cg.shared.global [%0], [%1], 16;" :: "r"(dst), "l"(src));
}
__device__ __forceinline__ void cp_commit() {
    asm volatile("cp.async.commit_group;" ::: "memory");
}
template<int N> __device__ __forceinline__ void cp_wait() {
    asm volatile("cp.async.wait_group %0;" :: "n"(N) : "memory");
}

#define LDSM_X4(r, addr) \
    asm volatile("ldmatrix.sync.aligned.m8n8.x4.shared.b16 {%0,%1,%2,%3}, [%4];" \
        : "=r"((r)[0]), "=r"((r)[1]), "=r"((r)[2]), "=r"((r)[3]) : "r"(addr))

__device__ __forceinline__ void mma16816(float* c, const uint32_t* a, const uint32_t* b) {
    asm volatile(
        "mma.sync.aligned.m16n8k16.row.col.f32.f16.f16.f32 "
        "{%0,%1,%2,%3}, {%4,%5,%6,%7}, {%8,%9}, {%0,%1,%2,%3};"
        : "+f"(c[0]), "+f"(c[1]), "+f"(c[2]), "+f"(c[3])
        : "r"(a[0]), "r"(a[1]), "r"(a[2]), "r"(a[3]), "r"(b[0]), "r"(b[1]));
}

// pack two f32 into f16x2 (v0 -> low half)
__device__ __forceinline__ uint32_t pack2h(float v0, float v1) {
    uint32_t r;
    asm("cvt.rn.f16x2.f32 %0, %1, %2;" : "=r"(r) : "f"(v1), "f"(v0));
    return r;
}
// hi/lo fp16 split of a float pair
__device__ __forceinline__ uint32_t split2h(float v0, float v1, uint32_t& lopack) {
    uint32_t hp = pack2h(v0, v1);
    float h0, h1;
    asm("{\n\t.reg .b16 a,b;\n\t"
        "mov.b32 {a,b}, %2;\n\t"
        "cvt.f32.f16 %0, a;\n\t"
        "cvt.f32.f16 %1, b;\n\t}"
        : "=f"(h0), "=f"(h1) : "r"(hp));
    lopack = pack2h(v0 - h0, v1 - h1);
    return hp;
}

// ---------------------------------------------------------------------------
// 2-pass GEMM mainloop: 128x128 tile, BK=32, 3-stage cp.async pipeline.
// acc += Ahi*Bhi + Ahi*Blo  (A hi-only; B carries hi+lo -> B exact to 2^-24)
// ---------------------------------------------------------------------------
#define PITCHB 80
#define AB128 (128 * PITCHB)
#define STAGE128 (3 * AB128)                 // Ahi + Bhi + Blo = 30720
#define SMEM_PROJ (3 * STAGE128)             // 92160

__device__ __forceinline__ void mma_mainloop128(
    uint32_t sb, float (&acc)[2][8][4],
    const fp16* __restrict__ Ahi, int lda, int arow0,
    const fp16* __restrict__ Bhi, const fp16* __restrict__ Blo, int ldb, int brow0,
    int nchunks)
{
    const int tid = threadIdx.x, lane = tid & 31, wid = tid >> 5;
    const int wm = (wid & 3) * 32, wn = (wid >> 2) * 64;

    auto load = [&](int c) {
        uint32_t s = sb + (uint32_t)(c % 3) * STAGE128;
        const int k0 = c * 32;
        for (int i = tid; i < 128 * 4; i += 256) {
            int r = i >> 2, cb = (i & 3) << 4;
            cp_async16(s + (uint32_t)(r * PITCHB + cb),
                       (const char*)(Ahi + (size_t)(arow0 + r) * lda + k0) + cb);
        }
        for (int i = tid; i < 128 * 4; i += 256) {
            int r = i >> 2, cb = (i & 3) << 4;
            uint32_t d = s + AB128 + (uint32_t)(r * PITCHB + cb);
            cp_async16(d,          (const char*)(Bhi + (size_t)(brow0 + r) * ldb + k0) + cb);
            cp_async16(d + AB128,  (const char*)(Blo + (size_t)(brow0 + r) * ldb + k0) + cb);
        }
        cp_commit();
    };

    const uint32_t aoff = (uint32_t)((wm + (lane & 15)) * PITCHB + ((lane & 16) ? 16 : 0));
    const uint32_t boff = (uint32_t)((wn + (lane & 7) + ((lane & 16) ? 8 : 0)) * PITCHB +
                                     ((lane & 8) ? 16 : 0));

    load(0);
    if (nchunks > 1) load(1);
    for (int c = 0; c < nchunks; c++) {
        if (c + 2 < nchunks) { load(c + 2); cp_wait<2>(); }
        else if (c + 1 < nchunks) cp_wait<1>();
        else cp_wait<0>();
        __syncthreads();
        uint32_t s  = sb + (uint32_t)(c % 3) * STAGE128;
        uint32_t sa = s + aoff;
        uint32_t sbb = s + AB128 + boff;
#pragma unroll
        for (int ks = 0; ks < 2; ks++) {
            const uint32_t ko = (uint32_t)(ks * 32);
            uint32_t ah[2][4];
            LDSM_X4(ah[0], sa + ko);
            LDSM_X4(ah[1], sa + 16 * PITCHB + ko);
            uint32_t bh[8][2], bl[8][2];
#pragma unroll
            for (int p = 0; p < 4; p++) {
                uint32_t r4[4];
                LDSM_X4(r4, sbb + (uint32_t)(p * 16 * PITCHB) + ko);
                bh[2*p][0] = r4[0]; bh[2*p][1] = r4[1];
                bh[2*p+1][0] = r4[2]; bh[2*p+1][1] = r4[3];
                LDSM_X4(r4, sbb + AB128 + (uint32_t)(p * 16 * PITCHB) + ko);
                bl[2*p][0] = r4[0]; bl[2*p][1] = r4[1];
                bl[2*p+1][0] = r4[2]; bl[2*p+1][1] = r4[3];
            }
#pragma unroll
            for (int f = 0; f < 2; f++)
#pragma unroll
                for (int j = 0; j < 8; j++)
                    mma16816(acc[f][j], ah[f], bh[j]);
#pragma unroll
            for (int f = 0; f < 2; f++)
#pragma unroll
                for (int j = 0; j < 8; j++)
                    mma16816(acc[f][j], ah[f], bl[j]);
        }
        __syncthreads();
    }
}

// ---------------------------------------------------------------------------
// Merged Q/K/V projections: grid(8, 16, 3). z: 0=Q (scale 0.125), 1=K, 2=V(T).
// Outputs hi/lo fp16 splits of the fp32 accumulator.
// ---------------------------------------------------------------------------
__global__ __launch_bounds__(256) void gemm_qkv(
    const float* __restrict__ bq, const float* __restrict__ bk, const float* __restrict__ bv)
{
    extern __shared__ char smem[];
    uint32_t sb = smem_u32(smem);
    const int z = blockIdx.z;
    const int row0 = blockIdx.y << 7, col0 = blockIdx.x << 7;

    const fp16* Ah = (z == 0) ? g_iq  : (z == 1) ? g_ik  : g_iv;
    const fp16* Bh = (z == 0) ? g_wqh : (z == 1) ? g_wkh : g_wvh;
    const fp16* Bl = (z == 0) ? g_wql : (z == 1) ? g_wkl : g_wvl;
    const float* bias = (z == 0) ? bq : (z == 1) ? bk : bv;
    const float scale = (z == 0) ? 0.125f : 1.0f;

    float acc[2][8][4];
#pragma unroll
    for (int f = 0; f < 2; f++)
#pragma unroll
        for (int j = 0; j < 8; j++)
#pragma unroll
            for (int q = 0; q < 4; q++) acc[f][j][q] = 0.f;

    mma_mainloop128(sb, acc, Ah, D_MODEL, row0, Bh, Bl, D_MODEL, col0, D_MODEL / 32);

    const int lane = threadIdx.x & 31, wid = threadIdx.x >> 5;
    const int wm = (wid & 3) * 32, wn = (wid >> 2) * 64;
    const int rb = row0 + wm + (lane >> 2);
    const int cb = col0 + wn + (lane & 3) * 2;
    fp16* ohi = (z == 0) ? g_qh : g_kh;
    fp16* olo = (z == 0) ? g_ql : g_kl;
#pragma unroll
    for (int f = 0; f < 2; f++)
#pragma unroll
        for (int j = 0; j < 8; j++)
#pragma unroll
            for (int rh = 0; rh < 2; rh++) {
                const int r = rb + f * 16 + rh * 8;
                const int col = cb + j * 8;
                float v0 = (acc[f][j][rh * 2 + 0] + bias[col])     * scale;
                float v1 = (acc[f][j][rh * 2 + 1] + bias[col + 1]) * scale;
                uint32_t lp, hp = split2h(v0, v1, lp);
                if (z < 2) {
                    *(uint32_t*)(ohi + (size_t)r * D_MODEL + col) = hp;
                    *(uint32_t*)(olo + (size_t)r * D_MODEL + col) = lp;
                } else {
                    g_vth[(size_t)col * S_LEN + r]       = __ushort_as_half((unsigned short)(hp & 0xffff));
                    g_vth[(size_t)(col + 1) * S_LEN + r] = __ushort_as_half((unsigned short)(hp >> 16));
                    g_vtl[(size_t)col * S_LEN + r]       = __ushort_as_half((unsigned short)(lp & 0xffff));
                    g_vtl[(size_t)(col + 1) * S_LEN + r] = __ushort_as_half((unsigned short)(lp >> 16));
                }
            }
}

// ---------------------------------------------------------------------------
// Output projection: Out = Zhi * (Wo_hi + Wo_lo)^T + badj  (fp32 out)
// ---------------------------------------------------------------------------
__global__ __launch_bounds__(256) void gemm_out(float* __restrict__ ofp)
{
    extern __shared__ char smem[];
    uint32_t sb = smem_u32(smem);
    const int row0 = blockIdx.y << 7, col0 = blockIdx.x << 7;
    float acc[2][8][4];
#pragma unroll
    for (int f = 0; f < 2; f++)
#pragma unroll
        for (int j = 0; j < 8; j++)
#pragma unroll
            for (int q = 0; q < 4; q++) acc[f][j][q] = 0.f;

    mma_mainloop128(sb, acc, g_zh, D_MODEL, row0, g_woh, g_wol, D_MODEL, col0, D_MODEL / 32);

    const int lane = threadIdx.x & 31, wid = threadIdx.x >> 5;
    const int wm = (wid & 3) * 32, wn = (wid >> 2) * 64;
    const int rb = row0 + wm + (lane >> 2);
    const int cb = col0 + wn + (lane & 3) * 2;
#pragma unroll
    for (int f = 0; f < 2; f++)
#pragma unroll
        for (int j = 0; j < 8; j++)
#pragma unroll
            for (int rh = 0; rh < 2; rh++) {
                const int r = rb + f * 16 + rh * 8;
                const int col = cb + j * 8;
                *(float2*)(ofp + (size_t)r * D_MODEL + col) = make_float2(
                    acc[f][j][rh * 2 + 0] + g_badj[col],
                    acc[f][j][rh * 2 + 1] + g_badj[col + 1]);
            }
}

// ---------------------------------------------------------------------------
// Fused attention. Q pre-scaled by 0.125.
// MMA1 (QK^T): 3-pass on q,k hi/lo (exp-sensitive).
// MMA2 (S@V):  2-pass, S as fp16 hi only.
// ---------------------------------------------------------------------------
#define PQB  144
#define PVB  272
#define QSZ  (128 * PQB)
#define KSTG (2 * QSZ)
#define VSZ  (64 * PVB)
#define VSTG (2 * VSZ)
#define OFF_K   (2 * QSZ)
#define OFF_V   (OFF_K + 2 * KSTG)
#define OFF_PART (OFF_V + 2 * VSTG)
#define FATTN_SMEM (OFF_PART + 8 * 128 * 4)

__global__ __launch_bounds__(256) void fused_attn()
{
    extern __shared__ char smem[];
    uint32_t sb = smem_u32(smem);
    const int h = blockIdx.y;
    const int tid = threadIdx.x, lane = tid & 31, wid = tid >> 5;
    float* spart = (float*)(smem + OFF_PART);

    const uint32_t qoff = sb + (uint32_t)((wid * 16 + (lane & 15)) * PQB + ((lane & 16) ? 16 : 0));
    const uint32_t kvlane = (uint32_t)((lane & 7) + ((lane & 16) ? 8 : 0));
    const uint32_t koff_l = kvlane * PQB + ((lane & 8) ? 16 : 0);
    const uint32_t voff_l = kvlane * PVB + ((lane & 8) ? 16 : 0);

    for (int half = 0; half < 2; half++) {
        const int sblk = half ? (15 - (int)blockIdx.x) : (int)blockIdx.x;
        const int row0 = sblk << 7;
        const int ntb  = sblk + 1;

        for (int i = tid; i < 128 * 8; i += 256) {
            int r = i >> 3, cbyte = (i & 7) << 4;
            cp_async16(sb + (uint32_t)(r * PQB) + cbyte,
                       (const char*)(g_qh + (size_t)(row0 + r) * D_MODEL + h * HDIM) + cbyte);
            cp_async16(sb + QSZ + (uint32_t)(r * PQB) + cbyte,
                       (const char*)(g_ql + (size_t)(row0 + r) * D_MODEL + h * HDIM) + cbyte);
        }
        cp_commit();

        auto loadKV = [&](int tb) {
            uint32_t kbase = sb + OFF_K + (uint32_t)(tb & 1) * KSTG;
            uint32_t vbase = sb + OFF_V + (uint32_t)(tb & 1) * VSTG;
            const int col0 = tb << 7;
            for (int i = tid; i < 128 * 8; i += 256) {
                int r = i >> 3, cbyte = (i & 7) << 4;
                cp_async16(kbase + (uint32_t)(r * PQB) + cbyte,
                           (const char*)(g_kh + (size_t)(col0 + r) * D_MODEL + h * HDIM) + cbyte);
                cp_async16(kbase + QSZ + (uint32_t)(r * PQB) + cbyte,
                           (const char*)(g_kl + (size_t)(col0 + r) * D_MODEL + h * HDIM) + cbyte);
            }
            for (int i = tid; i < 64 * 16; i += 256) {
                int r = i >> 4, cbyte = (i & 15) << 4;
                cp_async16(vbase + (uint32_t)(r * PVB) + cbyte,
                           (const char*)(g_vth + (size_t)(h * HDIM + r) * S_LEN + col0) + cbyte);
                cp_async16(vbase + VSZ + (uint32_t)(r * PVB) + cbyte,
                           (const char*)(g_vtl + (size_t)(h * HDIM + r) * S_LEN + col0) + cbyte);
            }
            cp_commit();
        };
        loadKV(0);

        float oacc[8][4];
#pragma unroll
        for (int j = 0; j < 8; j++)
#pragma unroll
            for (int q = 0; q < 4; q++) oacc[j][q] = 0.f;

        for (int tb = 0; tb < ntb; tb++) {
            if (tb + 1 < ntb) { loadKV(tb + 1); cp_wait<1>(); }
            else              { cp_wait<0>(); }
            __syncthreads();

            uint32_t kbase = sb + OFF_K + (uint32_t)(tb & 1) * KSTG;
            uint32_t vbase = sb + OFF_V + (uint32_t)(tb & 1) * VSTG;

            const bool diag = (tb == sblk);
            const int pmax  = diag ? (wid + 1) : 8;
            const int nfmax = diag ? (2 * wid + 2) : 16;

            // ---- MMA1: S[16 x 128] per warp, 3-pass ----
            float sacc[16][4];
#pragma unroll
            for (int j = 0; j < 16; j++)
#pragma unroll
                for (int q = 0; q < 4; q++) sacc[j][q] = 0.f;

            const uint32_t koff = kbase + koff_l;
#pragma unroll
            for (int ks = 0; ks < 4; ks++) {
                const uint32_t ko = (uint32_t)(ks * 32);
                uint32_t ah[4], al[4];
                LDSM_X4(ah, qoff + ko);
                LDSM_X4(al, qoff + QSZ + ko);
#pragma unroll
                for (int p = 0; p < 8; p++) {
                    if (p < pmax) {
                        uint32_t bh[4], bl[4];
                        LDSM_X4(bh, koff + (uint32_t)(p * 16 * PQB) + ko);
                        LDSM_X4(bl, koff + QSZ + (uint32_t)(p * 16 * PQB) + ko);
                        mma16816(sacc[2*p],   ah, bh);
                        mma16816(sacc[2*p+1], ah, bh + 2);
                        mma16816(sacc[2*p],   ah, bl);
                        mma16816(sacc[2*p+1], ah, bl + 2);
                        mma16816(sacc[2*p],   al, bh);
                        mma16816(sacc[2*p+1], al, bh + 2);
                    }
                }
            }

            // ---- mask + exp partial column sums (all MUFU) ----
            const int r0 = row0 + wid * 16 + (lane >> 2);
            const int r1 = r0 + 8;
            const int cb2 = (tb << 7) + 2 * (lane & 3);
#pragma unroll
            for (int nf = 0; nf < 16; nf++) {
                float eA = 0.f, eB = 0.f;
                if (nf < nfmax) {
                    const int c0 = cb2 + nf * 8;
                    float s0 = sacc[nf][0], s1 = sacc[nf][1];
                    float s2 = sacc[nf][2], s3 = sacc[nf][3];
                    bool m0 = true, m1 = true, m2 = true, m3 = true;
                    if (diag) {
                        m0 = (c0 <= r0); m1 = (c0 + 1 <= r0);
                        m2 = (c0 <= r1); m3 = (c0 + 1 <= r1);
                        s0 = m0 ? s0 : 0.f; s1 = m1 ? s1 : 0.f;
                        s2 = m2 ? s2 : 0.f; s3 = m3 ? s3 : 0.f;
                        sacc[nf][0] = s0; sacc[nf][1] = s1;
                        sacc[nf][2] = s2; sacc[nf][3] = s3;
                    }
                    float e0 = __expf(s0), e1 = __expf(s1);
                    float e2 = __expf(s2), e3 = __expf(s3);
                    if (diag) {
                        e0 = m0 ? e0 : 0.f; e1 = m1 ? e1 : 0.f;
                        e2 = m2 ? e2 : 0.f; e3 = m3 ? e3 : 0.f;
                    }
                    eA = e0 + e2; eB = e1 + e3;
                    eA += __shfl_xor_sync(0xffffffffu, eA, 4);
                    eA += __shfl_xor_sync(0xffffffffu, eA, 8);
                    eA += __shfl_xor_sync(0xffffffffu, eA, 16);
                    eB += __shfl_xor_sync(0xffffffffu, eB, 4);
                    eB += __shfl_xor_sync(0xffffffffu, eB, 8);
                    eB += __shfl_xor_sync(0xffffffffu, eB, 16);
                }
                if (lane < 4) {
                    spart[wid * 128 + nf * 8 + 2 * lane]     = eA;
                    spart[wid * 128 + nf * 8 + 2 * lane + 1] = eB;
                }
            }

            // ---- MMA2: O += S_hi @ (V_hi + V_lo)^T, 2-pass ----
            const uint32_t voff = vbase + voff_l;
#pragma unroll
            for (int kc = 0; kc < 8; kc++) {
                if (kc < pmax) {
                    uint32_t ahi[4];
                    ahi[0] = pack2h(sacc[2*kc][0],   sacc[2*kc][1]);
                    ahi[1] = pack2h(sacc[2*kc][2],   sacc[2*kc][3]);
                    ahi[2] = pack2h(sacc[2*kc+1][0], sacc[2*kc+1][1]);
                    ahi[3] = pack2h(sacc[2*kc+1][2], sacc[2*kc+1][3]);
                    const uint32_t ko = (uint32_t)(kc * 32);
#pragma unroll
                    for (int p = 0; p < 4; p++) {
                        uint32_t bh[4], bl[4];
                        LDSM_X4(bh, voff + (uint32_t)(p * 16 * PVB) + ko);
                        LDSM_X4(bl, voff + VSZ + (uint32_t)(p * 16 * PVB) + ko);
                        mma16816(oacc[2*p],   ahi, bh);
                        mma16816(oacc[2*p+1], ahi, bh + 2);
                        mma16816(oacc[2*p],   ahi, bl);
                        mma16816(oacc[2*p+1], ahi, bl + 2);
                    }
                }
            }

            __syncthreads();
            if (tid < 128) {
                float s = 0.f;
#pragma unroll
                for (int w = 0; w < 8; w++) s += spart[w * 128 + tid];
                g_part[((h * 16 + sblk) << 11) + (tb << 7) + tid] = s;
            }
        }

        // ---- epilogue: Z_hi = fp16(O)  (-c folded into out-proj bias) ----
        {
            const int r0 = row0 + wid * 16 + (lane >> 2);
            const int cb2 = 2 * (lane & 3);
#pragma unroll
            for (int nf = 0; nf < 8; nf++) {
                const int col = h * HDIM + nf * 8 + cb2;
                *(uint32_t*)(g_zh + (size_t)r0 * D_MODEL + col)       = pack2h(oacc[nf][0], oacc[nf][1]);
                *(uint32_t*)(g_zh + (size_t)(r0 + 8) * D_MODEL + col) = pack2h(oacc[nf][2], oacc[nf][3]);
            }
        }
        __syncthreads();
    }
}

// ---------------------------------------------------------------------------
// L[h][t] = log( t + sum_{sb>=tb} part[h][sb][t] )
// ---------------------------------------------------------------------------
__global__ __launch_bounds__(128) void lse_reduce()
{
    const int h = blockIdx.y, tb = blockIdx.x;
    const int t = (tb << 7) + threadIdx.x;
    float acc = (float)t;
    for (int sbk = tb; sbk < 16; sbk++)
        acc += g_part[((h * 16 + sbk) << 11) + t];
    g_L[h * S_LEN + t] = logf(acc);
}

// ---------------------------------------------------------------------------
// c[h][v] = sum_t L[h][t] * V[t][h*64+v]
// ---------------------------------------------------------------------------
__global__ __launch_bounds__(256) void compute_c_tc()
{
    __shared__ float part[4][HDIM];
    const int h = blockIdx.x;
    const int v = threadIdx.x & 63;
    const int g = threadIdx.x >> 6;
    const fp16* th = g_vth + (size_t)(h * HDIM + v) * S_LEN;
    const fp16* tl = g_vtl + (size_t)(h * HDIM + v) * S_LEN;
    const float* Lh = g_L + h * S_LEN;
    float sum = 0.f;
    const int t0 = g * (S_LEN / 4);
    for (int t = t0; t < t0 + S_LEN / 4; t++)
        sum = fmaf(Lh[t], __half2float(th[t]) + __half2float(tl[t]), sum);
    part[g][v] = sum;
    __syncthreads();
    if (g == 0)
        g_c[h * HDIM + v] = (part[0][v] + part[1][v]) + (part[2][v] + part[3][v]);
}

// ---------------------------------------------------------------------------
// b'[i] = WOb[i] - sum_j WOw[i][j] * c[j]
// ---------------------------------------------------------------------------
__global__ __launch_bounds__(256) void bias_adjust(
    const float* __restrict__ WOw, const float* __restrict__ WOb)
{
    const int lane = threadIdx.x & 31, wid = threadIdx.x >> 5;
    for (int rr = 0; rr < 4; rr++) {
        const int row = (blockIdx.x * 8 + wid) * 4 + rr;
        const float* wr = WOw + (size_t)row * D_MODEL;
        float s = 0.f;
        for (int j = lane; j < D_MODEL; j += 32)
            s = fmaf(wr[j], g_c[j], s);
#pragma unroll
        for (int o = 16; o > 0; o >>= 1) s += __shfl_xor_sync(0xffffffffu, s, o);
        if (lane == 0) g_badj[row] = WOb[row] - s;
    }
}

// ---------------------------------------------------------------------------
// One-shot split kernel. Blocks [0,3072): inputs -> hi only.
// Blocks [3072,5120): weights -> hi + lo. 8 floats per thread.
// ---------------------------------------------------------------------------
__global__ __launch_bounds__(256) void split_all(
    const float4* __restrict__ Qin, const float4* __restrict__ Kin, const float4* __restrict__ Vin,
    const float4* __restrict__ WQw, const float4* __restrict__ WKw,
    const float4* __restrict__ WVw, const float4* __restrict__ WOw)
{
    const int b = blockIdx.x;
    if (b < 3072) {
        const int t = b >> 10, rb = b & 1023;
        const float4* src = (t == 0) ? Qin : (t == 1) ? Kin : Vin;
        uint4* hi = (uint4*)((t == 0) ? g_iq : (t == 1) ? g_ik : g_iv);
        const int i = rb * 256 + threadIdx.x;
        float4 a = src[2 * i], c = src[2 * i + 1];
        hi[i] = make_uint4(pack2h(a.x, a.y), pack2h(a.z, a.w),
                           pack2h(c.x, c.y), pack2h(c.z, c.w));
    } else {
        const int bb = b - 3072, t = bb >> 9, rb = bb & 511;
        const float4* src = (t == 0) ? WQw : (t == 1) ? WKw : (t == 2) ? WVw : WOw;
        uint4* hi = (uint4*)((t == 0) ? g_wqh : (t == 1) ? g_wkh : (t == 2) ? g_wvh : g_woh);
        uint4* lo = (uint4*)((t == 0) ? g_wql : (t == 1) ? g_wkl : (t == 2) ? g_wvl : g_wol);
        const int i = rb * 256 + threadIdx.x;
        float4 a = src[2 * i], c = src[2 * i + 1];
        uint4 h, l;
        h.x = split2h(a.x, a.y, l.x);
        h.y = split2h(a.z, a.w, l.y);
        h.z = split2h(c.x, c.y, l.z);
        h.w = split2h(c.z, c.w, l.w);
        hi[i] = h;
        lo[i] = l;
    }
}

// ---------------------------------------------------------------------------
extern "C" void kernel_launch(void* const* d_in, const int* in_sizes, int n_in,
                              void* d_out, int out_size)
{
    const float* Qin = (const float*)d_in[0];
    const float* Kin = (const float*)d_in[1];
    const float* Vin = (const float*)d_in[2];
    const float* WQw = (const float*)d_in[3];
    const float* WQb = (const float*)d_in[4];
    const float* WKw = (const float*)d_in[5];
    const float* WKb = (const float*)d_in[6];
    const float* WVw = (const float*)d_in[7];
    const float* WVb = (const float*)d_in[8];
    const float* WOw = (const float*)d_in[9];
    const float* WOb = (const float*)d_in[10];
    float* Out = (float*)d_out;

    cudaFuncSetAttribute(gemm_qkv,  cudaFuncAttributeMaxDynamicSharedMemorySize, SMEM_PROJ);
    cudaFuncSetAttribute(gemm_out,  cudaFuncAttributeMaxDynamicSharedMemorySize, SMEM_PROJ);
    cudaFuncSetAttribute(fused_attn, cudaFuncAttributeMaxDynamicSharedMemorySize, FATTN_SMEM);

    dim3 blk(256);

    // 1) all splits in one launch
    split_all<<<5120, blk>>>((const float4*)Qin, (const float4*)Kin, (const float4*)Vin,
                             (const float4*)WQw, (const float4*)WKw,
                             (const float4*)WVw, (const float4*)WOw);

    // 2) Q/K/V projections (one launch, z = 0/1/2)
    dim3 gqkv(D_MODEL / 128, S_LEN / 128, 3);
    gemm_qkv<<<gqkv, blk, SMEM_PROJ>>>(WQb, WKb, WVb);

    // 3) fused attention
    dim3 gfa(8, NHEAD);
    fused_attn<<<gfa, blk, FATTN_SMEM>>>();

    // 4) L, c, adjusted bias
    dim3 glse(16, NHEAD);
    lse_reduce<<<glse, dim3(128)>>>();
    compute_c_tc<<<NHEAD, blk>>>();
    bias_adjust<<<32, blk>>>(WOw, WOb);

    // 5) output projection with folded bias
    dim3 gout(D_MODEL / 128, S_LEN / 128);
    gemm_out<<<gout, blk, SMEM_PROJ>>>(Out);
}

// round 8
// speedup vs baseline: 1.7228x; 1.3558x over previous
#include <cuda_runtime.h>
#include <cuda_fp16.h>
#include <stdint.h>
#include <math.h>

#define S_LEN   2048
#define D_MODEL 1024
#define NHEAD   16
#define HDIM    64

typedef __half fp16;

// ---------------------------------------------------------------------------
// Device-global scratch (allocation-free, zero-init at load).
// ---------------------------------------------------------------------------
static __device__ fp16  g_iq[S_LEN * D_MODEL], g_ik[S_LEN * D_MODEL], g_iv[S_LEN * D_MODEL];
static __device__ fp16  g_wq[D_MODEL * D_MODEL], g_wk[D_MODEL * D_MODEL];
static __device__ fp16  g_wv[D_MODEL * D_MODEL], g_wo[D_MODEL * D_MODEL];
static __device__ fp16  g_qh[S_LEN * D_MODEL], g_ql[S_LEN * D_MODEL];   // q hi/lo, pre-scaled 0.125
static __device__ fp16  g_kh[S_LEN * D_MODEL], g_kl[S_LEN * D_MODEL];   // k hi/lo
static __device__ fp16  g_vt[D_MODEL * S_LEN];                          // V^T hi [h*64+v][t]
static __device__ fp16  g_zh[S_LEN * D_MODEL];                          // Z hi
static __device__ float g_part[NHEAD * 16 * S_LEN];
static __device__ float g_L[NHEAD * S_LEN];
static __device__ float g_c[NHEAD * HDIM];
static __device__ float g_badj[D_MODEL];

// ---------------------------------------------------------------------------
// PTX helpers (generic sm_80-class PTX, legal under compute_103)
// ---------------------------------------------------------------------------
__device__ __forceinline__ uint32_t smem_u32(const void* p) {
    uint32_t a;
    asm("{ .reg .u64 t; cvta.to.shared.u64 t, %1; cvt.u32.u64 %0, t; }" : "=r"(a) : "l"(p));
    return a;
}
__device__ __forceinline__ void cp_async16(uint32_t dst, const void* src) {
    asm volatile("cp.async.cg.shared.global [%0], [%1], 16;" :: "r"(dst), "l"(src));
}
__device__ __forceinline__ void cp_commit() {
    asm volatile("cp.async.commit_group;" ::: "memory");
}
template<int N> __device__ __forceinline__ void cp_wait() {
    asm volatile("cp.async.wait_group %0;" :: "n"(N) : "memory");
}

#define LDSM_X4(r, addr) \
    asm volatile("ldmatrix.sync.aligned.m8n8.x4.shared.b16 {%0,%1,%2,%3}, [%4];" \
        : "=r"((r)[0]), "=r"((r)[1]), "=r"((r)[2]), "=r"((r)[3]) : "r"(addr))

__device__ __forceinline__ void mma16816(float* c, const uint32_t* a, const uint32_t* b) {
    asm volatile(
        "mma.sync.aligned.m16n8k16.row.col.f32.f16.f16.f32 "
        "{%0,%1,%2,%3}, {%4,%5,%6,%7}, {%8,%9}, {%0,%1,%2,%3};"
        : "+f"(c[0]), "+f"(c[1]), "+f"(c[2]), "+f"(c[3])
        : "r"(a[0]), "r"(a[1]), "r"(a[2]), "r"(a[3]), "r"(b[0]), "r"(b[1]));
}

__device__ __forceinline__ uint32_t pack2h(float v0, float v1) {
    uint32_t r;
    asm("cvt.rn.f16x2.f32 %0, %1, %2;" : "=r"(r) : "f"(v1), "f"(v0));
    return r;
}
__device__ __forceinline__ uint32_t split2h(float v0, float v1, uint32_t& lopack) {
    uint32_t hp = pack2h(v0, v1);
    float h0, h1;
    asm("{\n\t.reg .b16 a,b;\n\t"
        "mov.b32 {a,b}, %2;\n\t"
        "cvt.f32.f16 %0, a;\n\t"
        "cvt.f32.f16 %1, b;\n\t}"
        : "=f"(h0), "=f"(h1) : "r"(hp));
    lopack = pack2h(v0 - h0, v1 - h1);
    return hp;
}

// ---------------------------------------------------------------------------
// 1-pass GEMM mainloop: 128x128 tile, BK=32, 3-stage cp.async pipeline.
// acc += Ahi * Bhi
// ---------------------------------------------------------------------------
#define PITCHB 80
#define AB128 (128 * PITCHB)
#define STAGE1 (2 * AB128)             // 20480
#define SMEM_PROJ (3 * STAGE1)         // 61440

__device__ __forceinline__ void mma_mainloop128_1p(
    uint32_t sb, float (&acc)[2][8][4],
    const fp16* __restrict__ Ahi, int lda, int arow0,
    const fp16* __restrict__ Bhi, int ldb, int brow0,
    int nchunks)
{
    const int tid = threadIdx.x, lane = tid & 31, wid = tid >> 5;
    const int wm = (wid & 3) * 32, wn = (wid >> 2) * 64;

    auto load = [&](int c) {
        uint32_t s = sb + (uint32_t)(c % 3) * STAGE1;
        const int k0 = c * 32;
        for (int i = tid; i < 128 * 4; i += 256) {
            int r = i >> 2, cb = (i & 3) << 4;
            cp_async16(s + (uint32_t)(r * PITCHB + cb),
                       (const char*)(Ahi + (size_t)(arow0 + r) * lda + k0) + cb);
            cp_async16(s + AB128 + (uint32_t)(r * PITCHB + cb),
                       (const char*)(Bhi + (size_t)(brow0 + r) * ldb + k0) + cb);
        }
        cp_commit();
    };

    const uint32_t aoff = (uint32_t)((wm + (lane & 15)) * PITCHB + ((lane & 16) ? 16 : 0));
    const uint32_t boff = (uint32_t)((wn + (lane & 7) + ((lane & 16) ? 8 : 0)) * PITCHB +
                                     ((lane & 8) ? 16 : 0));

    load(0);
    if (nchunks > 1) load(1);
    for (int c = 0; c < nchunks; c++) {
        if (c + 2 < nchunks) { load(c + 2); cp_wait<2>(); }
        else if (c + 1 < nchunks) cp_wait<1>();
        else cp_wait<0>();
        __syncthreads();
        uint32_t s  = sb + (uint32_t)(c % 3) * STAGE1;
        uint32_t sa = s + aoff;
        uint32_t sbb = s + AB128 + boff;
#pragma unroll
        for (int ks = 0; ks < 2; ks++) {
            const uint32_t ko = (uint32_t)(ks * 32);
            uint32_t ah[2][4];
            LDSM_X4(ah[0], sa + ko);
            LDSM_X4(ah[1], sa + 16 * PITCHB + ko);
            uint32_t bh[8][2];
#pragma unroll
            for (int p = 0; p < 4; p++) {
                uint32_t r4[4];
                LDSM_X4(r4, sbb + (uint32_t)(p * 16 * PITCHB) + ko);
                bh[2*p][0] = r4[0]; bh[2*p][1] = r4[1];
                bh[2*p+1][0] = r4[2]; bh[2*p+1][1] = r4[3];
            }
#pragma unroll
            for (int f = 0; f < 2; f++)
#pragma unroll
                for (int j = 0; j < 8; j++)
                    mma16816(acc[f][j], ah[f], bh[j]);
        }
        __syncthreads();
    }
}

// ---------------------------------------------------------------------------
// Merged Q/K/V projections: grid(8, 16, 3). z: 0=Q (scale 0.125), 1=K, 2=V(T).
// Q/K write hi/lo splits; V writes transposed hi only.
// ---------------------------------------------------------------------------
__global__ __launch_bounds__(256) void gemm_qkv(
    const float* __restrict__ bq, const float* __restrict__ bk, const float* __restrict__ bv)
{
    extern __shared__ char smem[];
    uint32_t sb = smem_u32(smem);
    const int z = blockIdx.z;
    const int row0 = blockIdx.y << 7, col0 = blockIdx.x << 7;

    const fp16* Ah = (z == 0) ? g_iq : (z == 1) ? g_ik : g_iv;
    const fp16* Bh = (z == 0) ? g_wq : (z == 1) ? g_wk : g_wv;
    const float* bias = (z == 0) ? bq : (z == 1) ? bk : bv;
    const float scale = (z == 0) ? 0.125f : 1.0f;

    float acc[2][8][4];
#pragma unroll
    for (int f = 0; f < 2; f++)
#pragma unroll
        for (int j = 0; j < 8; j++)
#pragma unroll
            for (int q = 0; q < 4; q++) acc[f][j][q] = 0.f;

    mma_mainloop128_1p(sb, acc, Ah, D_MODEL, row0, Bh, D_MODEL, col0, D_MODEL / 32);

    const int lane = threadIdx.x & 31, wid = threadIdx.x >> 5;
    const int wm = (wid & 3) * 32, wn = (wid >> 2) * 64;
    const int rb = row0 + wm + (lane >> 2);
    const int cb = col0 + wn + (lane & 3) * 2;
    fp16* ohi = (z == 0) ? g_qh : g_kh;
    fp16* olo = (z == 0) ? g_ql : g_kl;
#pragma unroll
    for (int f = 0; f < 2; f++)
#pragma unroll
        for (int j = 0; j < 8; j++)
#pragma unroll
            for (int rh = 0; rh < 2; rh++) {
                const int r = rb + f * 16 + rh * 8;
                const int col = cb + j * 8;
                float v0 = (acc[f][j][rh * 2 + 0] + bias[col])     * scale;
                float v1 = (acc[f][j][rh * 2 + 1] + bias[col + 1]) * scale;
                if (z < 2) {
                    uint32_t lp, hp = split2h(v0, v1, lp);
                    *(uint32_t*)(ohi + (size_t)r * D_MODEL + col) = hp;
                    *(uint32_t*)(olo + (size_t)r * D_MODEL + col) = lp;
                } else {
                    uint32_t hp = pack2h(v0, v1);
                    g_vt[(size_t)col * S_LEN + r]       = __ushort_as_half((unsigned short)(hp & 0xffff));
                    g_vt[(size_t)(col + 1) * S_LEN + r] = __ushort_as_half((unsigned short)(hp >> 16));
                }
            }
}

// ---------------------------------------------------------------------------
// Output projection: Out = Zhi * Wo_hi^T + badj  (fp32 out)
// ---------------------------------------------------------------------------
__global__ __launch_bounds__(256) void gemm_out(float* __restrict__ ofp)
{
    extern __shared__ char smem[];
    uint32_t sb = smem_u32(smem);
    const int row0 = blockIdx.y << 7, col0 = blockIdx.x << 7;
    float acc[2][8][4];
#pragma unroll
    for (int f = 0; f < 2; f++)
#pragma unroll
        for (int j = 0; j < 8; j++)
#pragma unroll
            for (int q = 0; q < 4; q++) acc[f][j][q] = 0.f;

    mma_mainloop128_1p(sb, acc, g_zh, D_MODEL, row0, g_wo, D_MODEL, col0, D_MODEL / 32);

    const int lane = threadIdx.x & 31, wid = threadIdx.x >> 5;
    const int wm = (wid & 3) * 32, wn = (wid >> 2) * 64;
    const int rb = row0 + wm + (lane >> 2);
    const int cb = col0 + wn + (lane & 3) * 2;
#pragma unroll
    for (int f = 0; f < 2; f++)
#pragma unroll
        for (int j = 0; j < 8; j++)
#pragma unroll
            for (int rh = 0; rh < 2; rh++) {
                const int r = rb + f * 16 + rh * 8;
                const int col = cb + j * 8;
                *(float2*)(ofp + (size_t)r * D_MODEL + col) = make_float2(
                    acc[f][j][rh * 2 + 0] + g_badj[col],
                    acc[f][j][rh * 2 + 1] + g_badj[col + 1]);
            }
}

// ---------------------------------------------------------------------------
// Fused attention. Q pre-scaled by 0.125.
// MMA1 (QK^T): 3-pass on q,k hi/lo (exp-sensitive).
// MMA2 (S@V):  1-pass, S hi @ V hi.
// ---------------------------------------------------------------------------
#define PQB  144
#define PVB  272
#define QSZ  (128 * PQB)              // 18432
#define KSTG (2 * QSZ)                // 36864 (K hi+lo per stage)
#define VSZ  (64 * PVB)               // 17408 (V hi per stage)
#define OFF_K    (2 * QSZ)                        // 36864
#define OFF_V    (OFF_K + 2 * KSTG)               // 110592
#define OFF_PART (OFF_V + 2 * VSZ)                // 145408
#define FATTN_SMEM (OFF_PART + 8 * 128 * 4)       // 149504

__global__ __launch_bounds__(256) void fused_attn()
{
    extern __shared__ char smem[];
    uint32_t sb = smem_u32(smem);
    const int h = blockIdx.y;
    const int tid = threadIdx.x, lane = tid & 31, wid = tid >> 5;
    float* spart = (float*)(smem + OFF_PART);

    const uint32_t qoff = sb + (uint32_t)((wid * 16 + (lane & 15)) * PQB + ((lane & 16) ? 16 : 0));
    const uint32_t kvlane = (uint32_t)((lane & 7) + ((lane & 16) ? 8 : 0));
    const uint32_t koff_l = kvlane * PQB + ((lane & 8) ? 16 : 0);
    const uint32_t voff_l = kvlane * PVB + ((lane & 8) ? 16 : 0);

    for (int half = 0; half < 2; half++) {
        const int sblk = half ? (15 - (int)blockIdx.x) : (int)blockIdx.x;
        const int row0 = sblk << 7;
        const int ntb  = sblk + 1;

        for (int i = tid; i < 128 * 8; i += 256) {
            int r = i >> 3, cbyte = (i & 7) << 4;
            cp_async16(sb + (uint32_t)(r * PQB) + cbyte,
                       (const char*)(g_qh + (size_t)(row0 + r) * D_MODEL + h * HDIM) + cbyte);
            cp_async16(sb + QSZ + (uint32_t)(r * PQB) + cbyte,
                       (const char*)(g_ql + (size_t)(row0 + r) * D_MODEL + h * HDIM) + cbyte);
        }
        cp_commit();

        auto loadKV = [&](int tb) {
            uint32_t kbase = sb + OFF_K + (uint32_t)(tb & 1) * KSTG;
            uint32_t vbase = sb + OFF_V + (uint32_t)(tb & 1) * VSZ;
            const int col0 = tb << 7;
            for (int i = tid; i < 128 * 8; i += 256) {
                int r = i >> 3, cbyte = (i & 7) << 4;
                cp_async16(kbase + (uint32_t)(r * PQB) + cbyte,
                           (const char*)(g_kh + (size_t)(col0 + r) * D_MODEL + h * HDIM) + cbyte);
                cp_async16(kbase + QSZ + (uint32_t)(r * PQB) + cbyte,
                           (const char*)(g_kl + (size_t)(col0 + r) * D_MODEL + h * HDIM) + cbyte);
            }
            for (int i = tid; i < 64 * 16; i += 256) {
                int r = i >> 4, cbyte = (i & 15) << 4;
                cp_async16(vbase + (uint32_t)(r * PVB) + cbyte,
                           (const char*)(g_vt + (size_t)(h * HDIM + r) * S_LEN + col0) + cbyte);
            }
            cp_commit();
        };
        loadKV(0);

        float oacc[8][4];
#pragma unroll
        for (int j = 0; j < 8; j++)
#pragma unroll
            for (int q = 0; q < 4; q++) oacc[j][q] = 0.f;

        for (int tb = 0; tb < ntb; tb++) {
            if (tb + 1 < ntb) { loadKV(tb + 1); cp_wait<1>(); }
            else              { cp_wait<0>(); }
            __syncthreads();

            uint32_t kbase = sb + OFF_K + (uint32_t)(tb & 1) * KSTG;
            uint32_t vbase = sb + OFF_V + (uint32_t)(tb & 1) * VSZ;

            const bool diag = (tb == sblk);
            const int pmax  = diag ? (wid + 1) : 8;
            const int nfmax = diag ? (2 * wid + 2) : 16;

            // ---- MMA1: S[16 x 128] per warp, 3-pass ----
            float sacc[16][4];
#pragma unroll
            for (int j = 0; j < 16; j++)
#pragma unroll
                for (int q = 0; q < 4; q++) sacc[j][q] = 0.f;

            const uint32_t koff = kbase + koff_l;
#pragma unroll
            for (int ks = 0; ks < 4; ks++) {
                const uint32_t ko = (uint32_t)(ks * 32);
                uint32_t ah[4], al[4];
                LDSM_X4(ah, qoff + ko);
                LDSM_X4(al, qoff + QSZ + ko);
#pragma unroll
                for (int p = 0; p < 8; p++) {
                    if (p < pmax) {
                        uint32_t bh[4], bl[4];
                        LDSM_X4(bh, koff + (uint32_t)(p * 16 * PQB) + ko);
                        LDSM_X4(bl, koff + QSZ + (uint32_t)(p * 16 * PQB) + ko);
                        mma16816(sacc[2*p],   ah, bh);
                        mma16816(sacc[2*p+1], ah, bh + 2);
                        mma16816(sacc[2*p],   ah, bl);
                        mma16816(sacc[2*p+1], ah, bl + 2);
                        mma16816(sacc[2*p],   al, bh);
                        mma16816(sacc[2*p+1], al, bh + 2);
                    }
                }
            }

            // ---- mask + exp partial column sums (MUFU) ----
            const int r0 = row0 + wid * 16 + (lane >> 2);
            const int r1 = r0 + 8;
            const int cb2 = (tb << 7) + 2 * (lane & 3);
#pragma unroll
            for (int nf = 0; nf < 16; nf++) {
                float eA = 0.f, eB = 0.f;
                if (nf < nfmax) {
                    const int c0 = cb2 + nf * 8;
                    float s0 = sacc[nf][0], s1 = sacc[nf][1];
                    float s2 = sacc[nf][2], s3 = sacc[nf][3];
                    bool m0 = true, m1 = true, m2 = true, m3 = true;
                    if (diag) {
                        m0 = (c0 <= r0); m1 = (c0 + 1 <= r0);
                        m2 = (c0 <= r1); m3 = (c0 + 1 <= r1);
                        s0 = m0 ? s0 : 0.f; s1 = m1 ? s1 : 0.f;
                        s2 = m2 ? s2 : 0.f; s3 = m3 ? s3 : 0.f;
                        sacc[nf][0] = s0; sacc[nf][1] = s1;
                        sacc[nf][2] = s2; sacc[nf][3] = s3;
                    }
                    float e0 = __expf(s0), e1 = __expf(s1);
                    float e2 = __expf(s2), e3 = __expf(s3);
                    if (diag) {
                        e0 = m0 ? e0 : 0.f; e1 = m1 ? e1 : 0.f;
                        e2 = m2 ? e2 : 0.f; e3 = m3 ? e3 : 0.f;
                    }
                    eA = e0 + e2; eB = e1 + e3;
                    eA += __shfl_xor_sync(0xffffffffu, eA, 4);
                    eA += __shfl_xor_sync(0xffffffffu, eA, 8);
                    eA += __shfl_xor_sync(0xffffffffu, eA, 16);
                    eB += __shfl_xor_sync(0xffffffffu, eB, 4);
                    eB += __shfl_xor_sync(0xffffffffu, eB, 8);
                    eB += __shfl_xor_sync(0xffffffffu, eB, 16);
                }
                if (lane < 4) {
                    spart[wid * 128 + nf * 8 + 2 * lane]     = eA;
                    spart[wid * 128 + nf * 8 + 2 * lane + 1] = eB;
                }
            }

            // ---- MMA2: O += S_hi @ V_hi^T, 1-pass ----
            const uint32_t voff = vbase + voff_l;
#pragma unroll
            for (int kc = 0; kc < 8; kc++) {
                if (kc < pmax) {
                    uint32_t ahi[4];
                    ahi[0] = pack2h(sacc[2*kc][0],   sacc[2*kc][1]);
                    ahi[1] = pack2h(sacc[2*kc][2],   sacc[2*kc][3]);
                    ahi[2] = pack2h(sacc[2*kc+1][0], sacc[2*kc+1][1]);
                    ahi[3] = pack2h(sacc[2*kc+1][2], sacc[2*kc+1][3]);
                    const uint32_t ko = (uint32_t)(kc * 32);
#pragma unroll
                    for (int p = 0; p < 4; p++) {
                        uint32_t bh[4];
                        LDSM_X4(bh, voff + (uint32_t)(p * 16 * PVB) + ko);
                        mma16816(oacc[2*p],   ahi, bh);
                        mma16816(oacc[2*p+1], ahi, bh + 2);
                    }
                }
            }

            __syncthreads();
            if (tid < 128) {
                float s = 0.f;
#pragma unroll
                for (int w = 0; w < 8; w++) s += spart[w * 128 + tid];
                g_part[((h * 16 + sblk) << 11) + (tb << 7) + tid] = s;
            }
        }

        // ---- epilogue: Z_hi = fp16(O) ----
        {
            const int r0 = row0 + wid * 16 + (lane >> 2);
            const int cb2 = 2 * (lane & 3);
#pragma unroll
            for (int nf = 0; nf < 8; nf++) {
                const int col = h * HDIM + nf * 8 + cb2;
                *(uint32_t*)(g_zh + (size_t)r0 * D_MODEL + col)       = pack2h(oacc[nf][0], oacc[nf][1]);
                *(uint32_t*)(g_zh + (size_t)(r0 + 8) * D_MODEL + col) = pack2h(oacc[nf][2], oacc[nf][3]);
            }
        }
        __syncthreads();
    }
}

// ---------------------------------------------------------------------------
// L[h][t] = log( t + sum_{sb>=tb} part[h][sb][t] )
// ---------------------------------------------------------------------------
__global__ __launch_bounds__(128) void lse_reduce()
{
    const int h = blockIdx.y, tb = blockIdx.x;
    const int t = (tb << 7) + threadIdx.x;
    float acc = (float)t;
    for (int sbk = tb; sbk < 16; sbk++)
        acc += g_part[((h * 16 + sbk) << 11) + t];
    g_L[h * S_LEN + t] = logf(acc);
}

// ---------------------------------------------------------------------------
// c[h][v] = sum_t L[h][t] * V[t][h*64+v]   (V hi)
// ---------------------------------------------------------------------------
__global__ __launch_bounds__(256) void compute_c_tc()
{
    __shared__ float part[4][HDIM];
    const int h = blockIdx.x;
    const int v = threadIdx.x & 63;
    const int g = threadIdx.x >> 6;
    const fp16* th = g_vt + (size_t)(h * HDIM + v) * S_LEN;
    const float* Lh = g_L + h * S_LEN;
    float sum = 0.f;
    const int t0 = g * (S_LEN / 4);
    for (int t = t0; t < t0 + S_LEN / 4; t++)
        sum = fmaf(Lh[t], __half2float(th[t]), sum);
    part[g][v] = sum;
    __syncthreads();
    if (g == 0)
        g_c[h * HDIM + v] = (part[0][v] + part[1][v]) + (part[2][v] + part[3][v]);
}

// ---------------------------------------------------------------------------
// b'[i] = WOb[i] - sum_j WOw[i][j] * c[j]
// ---------------------------------------------------------------------------
__global__ __launch_bounds__(256) void bias_adjust(
    const float* __restrict__ WOw, const float* __restrict__ WOb)
{
    const int lane = threadIdx.x & 31, wid = threadIdx.x >> 5;
    for (int rr = 0; rr < 4; rr++) {
        const int row = (blockIdx.x * 8 + wid) * 4 + rr;
        const float* wr = WOw + (size_t)row * D_MODEL;
        float s = 0.f;
        for (int j = lane; j < D_MODEL; j += 32)
            s = fmaf(wr[j], g_c[j], s);
#pragma unroll
        for (int o = 16; o > 0; o >>= 1) s += __shfl_xor_sync(0xffffffffu, s, o);
        if (lane == 0) g_badj[row] = WOb[row] - s;
    }
}

// ---------------------------------------------------------------------------
// One-shot fp32 -> fp16 conversion: 3 inputs + 4 weights, hi only.
// 8 floats per thread.
// ---------------------------------------------------------------------------
__global__ __launch_bounds__(256) void split_all(
    const float4* __restrict__ Qin, const float4* __restrict__ Kin, const float4* __restrict__ Vin,
    const float4* __restrict__ WQw, const float4* __restrict__ WKw,
    const float4* __restrict__ WVw, const float4* __restrict__ WOw)
{
    const int b = blockIdx.x;
    const float4* src;
    uint4* hi;
    int rb;
    if (b < 3072) {
        const int t = b >> 10; rb = b & 1023;
        src = (t == 0) ? Qin : (t == 1) ? Kin : Vin;
        hi = (uint4*)((t == 0) ? g_iq : (t == 1) ? g_ik : g_iv);
    } else {
        const int bb = b - 3072, t = bb >> 9; rb = bb & 511;
        src = (t == 0) ? WQw : (t == 1) ? WKw : (t == 2) ? WVw : WOw;
        hi = (uint4*)((t == 0) ? g_wq : (t == 1) ? g_wk : (t == 2) ? g_wv : g_wo);
    }
    const int i = rb * 256 + threadIdx.x;
    float4 a = src[2 * i], c = src[2 * i + 1];
    hi[i] = make_uint4(pack2h(a.x, a.y), pack2h(a.z, a.w),
                       pack2h(c.x, c.y), pack2h(c.z, c.w));
}

// ---------------------------------------------------------------------------
extern "C" void kernel_launch(void* const* d_in, const int* in_sizes, int n_in,
                              void* d_out, int out_size)
{
    const float* Qin = (const float*)d_in[0];
    const float* Kin = (const float*)d_in[1];
    const float* Vin = (const float*)d_in[2];
    const float* WQw = (const float*)d_in[3];
    const float* WQb = (const float*)d_in[4];
    const float* WKw = (const float*)d_in[5];
    const float* WKb = (const float*)d_in[6];
    const float* WVw = (const float*)d_in[7];
    const float* WVb = (const float*)d_in[8];
    const float* WOw = (const float*)d_in[9];
    const float* WOb = (const float*)d_in[10];
    float* Out = (float*)d_out;

    cudaFuncSetAttribute(gemm_qkv,   cudaFuncAttributeMaxDynamicSharedMemorySize, SMEM_PROJ);
    cudaFuncSetAttribute(gemm_out,   cudaFuncAttributeMaxDynamicSharedMemorySize, SMEM_PROJ);
    cudaFuncSetAttribute(fused_attn, cudaFuncAttributeMaxDynamicSharedMemorySize, FATTN_SMEM);

    dim3 blk(256);

    // 1) fp16 conversions (one launch)
    split_all<<<5120, blk>>>((const float4*)Qin, (const float4*)Kin, (const float4*)Vin,
                             (const float4*)WQw, (const float4*)WKw,
                             (const float4*)WVw, (const float4*)WOw);

    // 2) Q/K/V projections (one launch, z = 0/1/2)
    dim3 gqkv(D_MODEL / 128, S_LEN / 128, 3);
    gemm_qkv<<<gqkv, blk, SMEM_PROJ>>>(WQb, WKb, WVb);

    // 3) fused attention
    dim3 gfa(8, NHEAD);
    fused_attn<<<gfa, blk, FATTN_SMEM>>>();

    // 4) L, c, adjusted bias
    dim3 glse(16, NHEAD);
    lse_reduce<<<glse, dim3(128)>>>();
    compute_c_tc<<<NHEAD, blk>>>();
    bias_adjust<<<32, blk>>>(WOw, WOb);

    // 5) output projection with folded bias
    dim3 gout(D_MODEL / 128, S_LEN / 128);
    gemm_out<<<gout, blk, SMEM_PROJ>>>(Out);
}

// round 9
// speedup vs baseline: 2.0508x; 1.1904x over previous
#include <cuda_runtime.h>
#include <cuda_fp16.h>
#include <stdint.h>
#include <math.h>

#define S_LEN   2048
#define D_MODEL 1024
#define NHEAD   16
#define HDIM    64

typedef __half fp16;

// ---------------------------------------------------------------------------
// Device-global scratch (allocation-free, zero-init at load).
// ---------------------------------------------------------------------------
static __device__ fp16  g_iq[S_LEN * D_MODEL], g_ik[S_LEN * D_MODEL], g_iv[S_LEN * D_MODEL];
static __device__ fp16  g_wq[D_MODEL * D_MODEL], g_wk[D_MODEL * D_MODEL];
static __device__ fp16  g_wv[D_MODEL * D_MODEL], g_wo[D_MODEL * D_MODEL];
static __device__ fp16  g_qh[S_LEN * D_MODEL];                          // q hi, pre-scaled 0.125
static __device__ fp16  g_kh[S_LEN * D_MODEL];                          // k hi
static __device__ fp16  g_vt[D_MODEL * S_LEN];                          // V^T hi [h*64+v][t]
static __device__ fp16  g_zh[S_LEN * D_MODEL];                          // Z hi
static __device__ float g_part[NHEAD * 16 * S_LEN];
static __device__ float g_L[NHEAD * S_LEN];
static __device__ float g_c[NHEAD * HDIM];
static __device__ float g_badj[D_MODEL];

// ---------------------------------------------------------------------------
// PTX helpers (generic sm_80-class PTX, legal under compute_103)
// ---------------------------------------------------------------------------
__device__ __forceinline__ uint32_t smem_u32(const void* p) {
    uint32_t a;
    asm("{ .reg .u64 t; cvta.to.shared.u64 t, %1; cvt.u32.u64 %0, t; }" : "=r"(a) : "l"(p));
    return a;
}
__device__ __forceinline__ void cp_async16(uint32_t dst, const void* src) {
    asm volatile("cp.async.cg.shared.global [%0], [%1], 16;" :: "r"(dst), "l"(src));
}
__device__ __forceinline__ void cp_commit() {
    asm volatile("cp.async.commit_group;" ::: "memory");
}
template<int N> __device__ __forceinline__ void cp_wait() {
    asm volatile("cp.async.wait_group %0;" :: "n"(N) : "memory");
}

#define LDSM_X4(r, addr) \
    asm volatile("ldmatrix.sync.aligned.m8n8.x4.shared.b16 {%0,%1,%2,%3}, [%4];" \
        : "=r"((r)[0]), "=r"((r)[1]), "=r"((r)[2]), "=r"((r)[3]) : "r"(addr))

__device__ __forceinline__ void mma16816(float* c, const uint32_t* a, const uint32_t* b) {
    asm volatile(
        "mma.sync.aligned.m16n8k16.row.col.f32.f16.f16.f32 "
        "{%0,%1,%2,%3}, {%4,%5,%6,%7}, {%8,%9}, {%0,%1,%2,%3};"
        : "+f"(c[0]), "+f"(c[1]), "+f"(c[2]), "+f"(c[3])
        : "r"(a[0]), "r"(a[1]), "r"(a[2]), "r"(a[3]), "r"(b[0]), "r"(b[1]));
}

__device__ __forceinline__ uint32_t pack2h(float v0, float v1) {
    uint32_t r;
    asm("cvt.rn.f16x2.f32 %0, %1, %2;" : "=r"(r) : "f"(v1), "f"(v0));
    return r;
}

// ---------------------------------------------------------------------------
// 1-pass GEMM mainloop: 128x128 tile, BK=32, 3-stage cp.async pipeline.
// acc += Ahi * Bhi
// ---------------------------------------------------------------------------
#define PITCHB 80
#define AB128 (128 * PITCHB)
#define STAGE1 (2 * AB128)             // 20480
#define SMEM_PROJ (3 * STAGE1)         // 61440

__device__ __forceinline__ void mma_mainloop128_1p(
    uint32_t sb, float (&acc)[2][8][4],
    const fp16* __restrict__ Ahi, int lda, int arow0,
    const fp16* __restrict__ Bhi, int ldb, int brow0,
    int nchunks)
{
    const int tid = threadIdx.x, lane = tid & 31, wid = tid >> 5;
    const int wm = (wid & 3) * 32, wn = (wid >> 2) * 64;

    auto load = [&](int c) {
        uint32_t s = sb + (uint32_t)(c % 3) * STAGE1;
        const int k0 = c * 32;
        for (int i = tid; i < 128 * 4; i += 256) {
            int r = i >> 2, cb = (i & 3) << 4;
            cp_async16(s + (uint32_t)(r * PITCHB + cb),
                       (const char*)(Ahi + (size_t)(arow0 + r) * lda + k0) + cb);
            cp_async16(s + AB128 + (uint32_t)(r * PITCHB + cb),
                       (const char*)(Bhi + (size_t)(brow0 + r) * ldb + k0) + cb);
        }
        cp_commit();
    };

    const uint32_t aoff = (uint32_t)((wm + (lane & 15)) * PITCHB + ((lane & 16) ? 16 : 0));
    const uint32_t boff = (uint32_t)((wn + (lane & 7) + ((lane & 16) ? 8 : 0)) * PITCHB +
                                     ((lane & 8) ? 16 : 0));

    load(0);
    if (nchunks > 1) load(1);
    for (int c = 0; c < nchunks; c++) {
        if (c + 2 < nchunks) { load(c + 2); cp_wait<2>(); }
        else if (c + 1 < nchunks) cp_wait<1>();
        else cp_wait<0>();
        __syncthreads();
        uint32_t s  = sb + (uint32_t)(c % 3) * STAGE1;
        uint32_t sa = s + aoff;
        uint32_t sbb = s + AB128 + boff;
#pragma unroll
        for (int ks = 0; ks < 2; ks++) {
            const uint32_t ko = (uint32_t)(ks * 32);
            uint32_t ah[2][4];
            LDSM_X4(ah[0], sa + ko);
            LDSM_X4(ah[1], sa + 16 * PITCHB + ko);
            uint32_t bh[8][2];
#pragma unroll
            for (int p = 0; p < 4; p++) {
                uint32_t r4[4];
                LDSM_X4(r4, sbb + (uint32_t)(p * 16 * PITCHB) + ko);
                bh[2*p][0] = r4[0]; bh[2*p][1] = r4[1];
                bh[2*p+1][0] = r4[2]; bh[2*p+1][1] = r4[3];
            }
#pragma unroll
            for (int f = 0; f < 2; f++)
#pragma unroll
                for (int j = 0; j < 8; j++)
                    mma16816(acc[f][j], ah[f], bh[j]);
        }
        __syncthreads();
    }
}

// ---------------------------------------------------------------------------
// Merged Q/K/V projections: grid(8, 16, 3). z: 0=Q (scale 0.125), 1=K, 2=V(T).
// All outputs fp16 hi only; V transposed.
// ---------------------------------------------------------------------------
__global__ __launch_bounds__(256) void gemm_qkv(
    const float* __restrict__ bq, const float* __restrict__ bk, const float* __restrict__ bv)
{
    extern __shared__ char smem[];
    uint32_t sb = smem_u32(smem);
    const int z = blockIdx.z;
    const int row0 = blockIdx.y << 7, col0 = blockIdx.x << 7;

    const fp16* Ah = (z == 0) ? g_iq : (z == 1) ? g_ik : g_iv;
    const fp16* Bh = (z == 0) ? g_wq : (z == 1) ? g_wk : g_wv;
    const float* bias = (z == 0) ? bq : (z == 1) ? bk : bv;
    const float scale = (z == 0) ? 0.125f : 1.0f;

    float acc[2][8][4];
#pragma unroll
    for (int f = 0; f < 2; f++)
#pragma unroll
        for (int j = 0; j < 8; j++)
#pragma unroll
            for (int q = 0; q < 4; q++) acc[f][j][q] = 0.f;

    mma_mainloop128_1p(sb, acc, Ah, D_MODEL, row0, Bh, D_MODEL, col0, D_MODEL / 32);

    const int lane = threadIdx.x & 31, wid = threadIdx.x >> 5;
    const int wm = (wid & 3) * 32, wn = (wid >> 2) * 64;
    const int rb = row0 + wm + (lane >> 2);
    const int cb = col0 + wn + (lane & 3) * 2;
    fp16* ohi = (z == 0) ? g_qh : g_kh;
#pragma unroll
    for (int f = 0; f < 2; f++)
#pragma unroll
        for (int j = 0; j < 8; j++)
#pragma unroll
            for (int rh = 0; rh < 2; rh++) {
                const int r = rb + f * 16 + rh * 8;
                const int col = cb + j * 8;
                float v0 = (acc[f][j][rh * 2 + 0] + bias[col])     * scale;
                float v1 = (acc[f][j][rh * 2 + 1] + bias[col + 1]) * scale;
                uint32_t hp = pack2h(v0, v1);
                if (z < 2) {
                    *(uint32_t*)(ohi + (size_t)r * D_MODEL + col) = hp;
                } else {
                    g_vt[(size_t)col * S_LEN + r]       = __ushort_as_half((unsigned short)(hp & 0xffff));
                    g_vt[(size_t)(col + 1) * S_LEN + r] = __ushort_as_half((unsigned short)(hp >> 16));
                }
            }
}

// ---------------------------------------------------------------------------
// Output projection: Out = Zhi * Wo_hi^T + badj  (fp32 out)
// ---------------------------------------------------------------------------
__global__ __launch_bounds__(256) void gemm_out(float* __restrict__ ofp)
{
    extern __shared__ char smem[];
    uint32_t sb = smem_u32(smem);
    const int row0 = blockIdx.y << 7, col0 = blockIdx.x << 7;
    float acc[2][8][4];
#pragma unroll
    for (int f = 0; f < 2; f++)
#pragma unroll
        for (int j = 0; j < 8; j++)
#pragma unroll
            for (int q = 0; q < 4; q++) acc[f][j][q] = 0.f;

    mma_mainloop128_1p(sb, acc, g_zh, D_MODEL, row0, g_wo, D_MODEL, col0, D_MODEL / 32);

    const int lane = threadIdx.x & 31, wid = threadIdx.x >> 5;
    const int wm = (wid & 3) * 32, wn = (wid >> 2) * 64;
    const int rb = row0 + wm + (lane >> 2);
    const int cb = col0 + wn + (lane & 3) * 2;
#pragma unroll
    for (int f = 0; f < 2; f++)
#pragma unroll
        for (int j = 0; j < 8; j++)
#pragma unroll
            for (int rh = 0; rh < 2; rh++) {
                const int r = rb + f * 16 + rh * 8;
                const int col = cb + j * 8;
                *(float2*)(ofp + (size_t)r * D_MODEL + col) = make_float2(
                    acc[f][j][rh * 2 + 0] + g_badj[col],
                    acc[f][j][rh * 2 + 1] + g_badj[col + 1]);
            }
}

// ---------------------------------------------------------------------------
// Fused attention. Q pre-scaled by 0.125. MMA1 and MMA2 both 1-pass fp16-hi.
// ---------------------------------------------------------------------------
#define PQB  144
#define PVB  272
#define QSZ  (128 * PQB)              // 18432
#define VSZ  (64 * PVB)               // 17408
#define OFF_K    QSZ                              // 18432 (K hi, 2 stages)
#define OFF_V    (OFF_K + 2 * QSZ)                // 55296 (V hi, 2 stages)
#define OFF_PART (OFF_V + 2 * VSZ)                // 90112
#define FATTN_SMEM (OFF_PART + 8 * 128 * 4)       // 94208

__global__ __launch_bounds__(256) void fused_attn()
{
    extern __shared__ char smem[];
    uint32_t sb = smem_u32(smem);
    const int h = blockIdx.y;
    const int tid = threadIdx.x, lane = tid & 31, wid = tid >> 5;
    float* spart = (float*)(smem + OFF_PART);

    const uint32_t qoff = sb + (uint32_t)((wid * 16 + (lane & 15)) * PQB + ((lane & 16) ? 16 : 0));
    const uint32_t kvlane = (uint32_t)((lane & 7) + ((lane & 16) ? 8 : 0));
    const uint32_t koff_l = kvlane * PQB + ((lane & 8) ? 16 : 0);
    const uint32_t voff_l = kvlane * PVB + ((lane & 8) ? 16 : 0);

    for (int half = 0; half < 2; half++) {
        const int sblk = half ? (15 - (int)blockIdx.x) : (int)blockIdx.x;
        const int row0 = sblk << 7;
        const int ntb  = sblk + 1;

        // Q tile (hi only)
        for (int i = tid; i < 128 * 8; i += 256) {
            int r = i >> 3, cbyte = (i & 7) << 4;
            cp_async16(sb + (uint32_t)(r * PQB) + cbyte,
                       (const char*)(g_qh + (size_t)(row0 + r) * D_MODEL + h * HDIM) + cbyte);
        }
        cp_commit();

        auto loadKV = [&](int tb) {
            uint32_t kbase = sb + OFF_K + (uint32_t)(tb & 1) * QSZ;
            uint32_t vbase = sb + OFF_V + (uint32_t)(tb & 1) * VSZ;
            const int col0 = tb << 7;
            for (int i = tid; i < 128 * 8; i += 256) {
                int r = i >> 3, cbyte = (i & 7) << 4;
                cp_async16(kbase + (uint32_t)(r * PQB) + cbyte,
                           (const char*)(g_kh + (size_t)(col0 + r) * D_MODEL + h * HDIM) + cbyte);
            }
            for (int i = tid; i < 64 * 16; i += 256) {
                int r = i >> 4, cbyte = (i & 15) << 4;
                cp_async16(vbase + (uint32_t)(r * PVB) + cbyte,
                           (const char*)(g_vt + (size_t)(h * HDIM + r) * S_LEN + col0) + cbyte);
            }
            cp_commit();
        };
        loadKV(0);

        float oacc[8][4];
#pragma unroll
        for (int j = 0; j < 8; j++)
#pragma unroll
            for (int q = 0; q < 4; q++) oacc[j][q] = 0.f;

        for (int tb = 0; tb < ntb; tb++) {
            if (tb + 1 < ntb) { loadKV(tb + 1); cp_wait<1>(); }
            else              { cp_wait<0>(); }
            __syncthreads();

            uint32_t kbase = sb + OFF_K + (uint32_t)(tb & 1) * QSZ;
            uint32_t vbase = sb + OFF_V + (uint32_t)(tb & 1) * VSZ;

            const bool diag = (tb == sblk);
            const int pmax  = diag ? (wid + 1) : 8;
            const int nfmax = diag ? (2 * wid + 2) : 16;

            // ---- MMA1: S[16 x 128] per warp, 1-pass ----
            float sacc[16][4];
#pragma unroll
            for (int j = 0; j < 16; j++)
#pragma unroll
                for (int q = 0; q < 4; q++) sacc[j][q] = 0.f;

            const uint32_t koff = kbase + koff_l;
#pragma unroll
            for (int ks = 0; ks < 4; ks++) {
                const uint32_t ko = (uint32_t)(ks * 32);
                uint32_t ah[4];
                LDSM_X4(ah, qoff + ko);
#pragma unroll
                for (int p = 0; p < 8; p++) {
                    if (p < pmax) {
                        uint32_t bh[4];
                        LDSM_X4(bh, koff + (uint32_t)(p * 16 * PQB) + ko);
                        mma16816(sacc[2*p],   ah, bh);
                        mma16816(sacc[2*p+1], ah, bh + 2);
                    }
                }
            }

            // ---- mask + exp partial column sums (MUFU) ----
            const int r0 = row0 + wid * 16 + (lane >> 2);
            const int r1 = r0 + 8;
            const int cb2 = (tb << 7) + 2 * (lane & 3);
#pragma unroll
            for (int nf = 0; nf < 16; nf++) {
                float eA = 0.f, eB = 0.f;
                if (nf < nfmax) {
                    const int c0 = cb2 + nf * 8;
                    float s0 = sacc[nf][0], s1 = sacc[nf][1];
                    float s2 = sacc[nf][2], s3 = sacc[nf][3];
                    bool m0 = true, m1 = true, m2 = true, m3 = true;
                    if (diag) {
                        m0 = (c0 <= r0); m1 = (c0 + 1 <= r0);
                        m2 = (c0 <= r1); m3 = (c0 + 1 <= r1);
                        s0 = m0 ? s0 : 0.f; s1 = m1 ? s1 : 0.f;
                        s2 = m2 ? s2 : 0.f; s3 = m3 ? s3 : 0.f;
                        sacc[nf][0] = s0; sacc[nf][1] = s1;
                        sacc[nf][2] = s2; sacc[nf][3] = s3;
                    }
                    float e0 = __expf(s0), e1 = __expf(s1);
                    float e2 = __expf(s2), e3 = __expf(s3);
                    if (diag) {
                        e0 = m0 ? e0 : 0.f; e1 = m1 ? e1 : 0.f;
                        e2 = m2 ? e2 : 0.f; e3 = m3 ? e3 : 0.f;
                    }
                    eA = e0 + e2; eB = e1 + e3;
                    eA += __shfl_xor_sync(0xffffffffu, eA, 4);
                    eA += __shfl_xor_sync(0xffffffffu, eA, 8);
                    eA += __shfl_xor_sync(0xffffffffu, eA, 16);
                    eB += __shfl_xor_sync(0xffffffffu, eB, 4);
                    eB += __shfl_xor_sync(0xffffffffu, eB, 8);
                    eB += __shfl_xor_sync(0xffffffffu, eB, 16);
                }
                if (lane < 4) {
                    spart[wid * 128 + nf * 8 + 2 * lane]     = eA;
                    spart[wid * 128 + nf * 8 + 2 * lane + 1] = eB;
                }
            }

            // ---- MMA2: O += S_hi @ V_hi^T, 1-pass ----
            const uint32_t voff = vbase + voff_l;
#pragma unroll
            for (int kc = 0; kc < 8; kc++) {
                if (kc < pmax) {
                    uint32_t ahi[4];
                    ahi[0] = pack2h(sacc[2*kc][0],   sacc[2*kc][1]);
                    ahi[1] = pack2h(sacc[2*kc][2],   sacc[2*kc][3]);
                    ahi[2] = pack2h(sacc[2*kc+1][0], sacc[2*kc+1][1]);
                    ahi[3] = pack2h(sacc[2*kc+1][2], sacc[2*kc+1][3]);
                    const uint32_t ko = (uint32_t)(kc * 32);
#pragma unroll
                    for (int p = 0; p < 4; p++) {
                        uint32_t bh[4];
                        LDSM_X4(bh, voff + (uint32_t)(p * 16 * PVB) + ko);
                        mma16816(oacc[2*p],   ahi, bh);
                        mma16816(oacc[2*p+1], ahi, bh + 2);
                    }
                }
            }

            __syncthreads();
            if (tid < 128) {
                float s = 0.f;
#pragma unroll
                for (int w = 0; w < 8; w++) s += spart[w * 128 + tid];
                g_part[((h * 16 + sblk) << 11) + (tb << 7) + tid] = s;
            }
        }

        // ---- epilogue: Z_hi = fp16(O) ----
        {
            const int r0 = row0 + wid * 16 + (lane >> 2);
            const int cb2 = 2 * (lane & 3);
#pragma unroll
            for (int nf = 0; nf < 8; nf++) {
                const int col = h * HDIM + nf * 8 + cb2;
                *(uint32_t*)(g_zh + (size_t)r0 * D_MODEL + col)       = pack2h(oacc[nf][0], oacc[nf][1]);
                *(uint32_t*)(g_zh + (size_t)(r0 + 8) * D_MODEL + col) = pack2h(oacc[nf][2], oacc[nf][3]);
            }
        }
        __syncthreads();
    }
}

// ---------------------------------------------------------------------------
// L[h][t] = log( t + sum_{sb>=tb} part[h][sb][t] )
// ---------------------------------------------------------------------------
__global__ __launch_bounds__(128) void lse_reduce()
{
    const int h = blockIdx.y, tb = blockIdx.x;
    const int t = (tb << 7) + threadIdx.x;
    float acc = (float)t;
    for (int sbk = tb; sbk < 16; sbk++)
        acc += g_part[((h * 16 + sbk) << 11) + t];
    g_L[h * S_LEN + t] = logf(acc);
}

// ---------------------------------------------------------------------------
// c[h][v] = sum_t L[h][t] * V[t][h*64+v]   (V hi)
// ---------------------------------------------------------------------------
__global__ __launch_bounds__(256) void compute_c_tc()
{
    __shared__ float part[4][HDIM];
    const int h = blockIdx.x;
    const int v = threadIdx.x & 63;
    const int g = threadIdx.x >> 6;
    const fp16* th = g_vt + (size_t)(h * HDIM + v) * S_LEN;
    const float* Lh = g_L + h * S_LEN;
    float sum = 0.f;
    const int t0 = g * (S_LEN / 4);
    for (int t = t0; t < t0 + S_LEN / 4; t++)
        sum = fmaf(Lh[t], __half2float(th[t]), sum);
    part[g][v] = sum;
    __syncthreads();
    if (g == 0)
        g_c[h * HDIM + v] = (part[0][v] + part[1][v]) + (part[2][v] + part[3][v]);
}

// ---------------------------------------------------------------------------
// b'[i] = WOb[i] - sum_j WOw[i][j] * c[j]
// ---------------------------------------------------------------------------
__global__ __launch_bounds__(256) void bias_adjust(
    const float* __restrict__ WOw, const float* __restrict__ WOb)
{
    const int lane = threadIdx.x & 31, wid = threadIdx.x >> 5;
    for (int rr = 0; rr < 4; rr++) {
        const int row = (blockIdx.x * 8 + wid) * 4 + rr;
        const float* wr = WOw + (size_t)row * D_MODEL;
        float s = 0.f;
        for (int j = lane; j < D_MODEL; j += 32)
            s = fmaf(wr[j], g_c[j], s);
#pragma unroll
        for (int o = 16; o > 0; o >>= 1) s += __shfl_xor_sync(0xffffffffu, s, o);
        if (lane == 0) g_badj[row] = WOb[row] - s;
    }
}

// ---------------------------------------------------------------------------
// One-shot fp32 -> fp16 conversion: 3 inputs + 4 weights, hi only.
// ---------------------------------------------------------------------------
__global__ __launch_bounds__(256) void split_all(
    const float4* __restrict__ Qin, const float4* __restrict__ Kin, const float4* __restrict__ Vin,
    const float4* __restrict__ WQw, const float4* __restrict__ WKw,
    const float4* __restrict__ WVw, const float4* __restrict__ WOw)
{
    const int b = blockIdx.x;
    const float4* src;
    uint4* hi;
    int rb;
    if (b < 3072) {
        const int t = b >> 10; rb = b & 1023;
        src = (t == 0) ? Qin : (t == 1) ? Kin : Vin;
        hi = (uint4*)((t == 0) ? g_iq : (t == 1) ? g_ik : g_iv);
    } else {
        const int bb = b - 3072, t = bb >> 9; rb = bb & 511;
        src = (t == 0) ? WQw : (t == 1) ? WKw : (t == 2) ? WVw : WOw;
        hi = (uint4*)((t == 0) ? g_wq : (t == 1) ? g_wk : (t == 2) ? g_wv : g_wo);
    }
    const int i = rb * 256 + threadIdx.x;
    float4 a = src[2 * i], c = src[2 * i + 1];
    hi[i] = make_uint4(pack2h(a.x, a.y), pack2h(a.z, a.w),
                       pack2h(c.x, c.y), pack2h(c.z, c.w));
}

// ---------------------------------------------------------------------------
extern "C" void kernel_launch(void* const* d_in, const int* in_sizes, int n_in,
                              void* d_out, int out_size)
{
    const float* Qin = (const float*)d_in[0];
    const float* Kin = (const float*)d_in[1];
    const float* Vin = (const float*)d_in[2];
    const float* WQw = (const float*)d_in[3];
    const float* WQb = (const float*)d_in[4];
    const float* WKw = (const float*)d_in[5];
    const float* WKb = (const float*)d_in[6];
    const float* WVw = (const float*)d_in[7];
    const float* WVb = (const float*)d_in[8];
    const float* WOw = (const float*)d_in[9];
    const float* WOb = (const float*)d_in[10];
    float* Out = (float*)d_out;

    cudaFuncSetAttribute(gemm_qkv,   cudaFuncAttributeMaxDynamicSharedMemorySize, SMEM_PROJ);
    cudaFuncSetAttribute(gemm_out,   cudaFuncAttributeMaxDynamicSharedMemorySize, SMEM_PROJ);
    cudaFuncSetAttribute(fused_attn, cudaFuncAttributeMaxDynamicSharedMemorySize, FATTN_SMEM);

    dim3 blk(256);

    // 1) fp16 conversions
    split_all<<<5120, blk>>>((const float4*)Qin, (const float4*)Kin, (const float4*)Vin,
                             (const float4*)WQw, (const float4*)WKw,
                             (const float4*)WVw, (const float4*)WOw);

    // 2) Q/K/V projections
    dim3 gqkv(D_MODEL / 128, S_LEN / 128, 3);
    gemm_qkv<<<gqkv, blk, SMEM_PROJ>>>(WQb, WKb, WVb);

    // 3) fused attention
    dim3 gfa(8, NHEAD);
    fused_attn<<<gfa, blk, FATTN_SMEM>>>();

    // 4) L, c, adjusted bias
    dim3 glse(16, NHEAD);
    lse_reduce<<<glse, dim3(128)>>>();
    compute_c_tc<<<NHEAD, blk>>>();
    bias_adjust<<<32, blk>>>(WOw, WOb);

    // 5) output projection with folded bias
    dim3 gout(D_MODEL / 128, S_LEN / 128);
    gemm_out<<<gout, blk, SMEM_PROJ>>>(Out);
}

// round 10
// speedup vs baseline: 2.1186x; 1.0330x over previous
#include <cuda_runtime.h>
#include <cuda_fp16.h>
#include <stdint.h>
#include <math.h>

#define S_LEN   2048
#define D_MODEL 1024
#define NHEAD   16
#define HDIM    64

typedef __half fp16;

// ---------------------------------------------------------------------------
// Device-global scratch (allocation-free, zero-init at load).
// ---------------------------------------------------------------------------
static __device__ fp16  g_iq[S_LEN * D_MODEL], g_ik[S_LEN * D_MODEL], g_iv[S_LEN * D_MODEL];
static __device__ fp16  g_wq[D_MODEL * D_MODEL], g_wk[D_MODEL * D_MODEL];
static __device__ fp16  g_wv[D_MODEL * D_MODEL], g_wo[D_MODEL * D_MODEL];
static __device__ fp16  g_qh[S_LEN * D_MODEL];                          // q hi, pre-scaled 0.125
static __device__ fp16  g_kh[S_LEN * D_MODEL];                          // k hi
static __device__ fp16  g_vt[D_MODEL * S_LEN];                          // V^T hi [h*64+v][t]
static __device__ fp16  g_zh[S_LEN * D_MODEL];                          // Z hi
static __device__ float g_part[NHEAD * 16 * S_LEN];
static __device__ float g_L[NHEAD * S_LEN];
static __device__ float g_c[NHEAD * HDIM];
static __device__ float g_badj[D_MODEL];

// ---------------------------------------------------------------------------
// PTX helpers (generic sm_80-class PTX, legal under compute_103)
// ---------------------------------------------------------------------------
__device__ __forceinline__ uint32_t smem_u32(const void* p) {
    uint32_t a;
    asm("{ .reg .u64 t; cvta.to.shared.u64 t, %1; cvt.u32.u64 %0, t; }" : "=r"(a) : "l"(p));
    return a;
}
__device__ __forceinline__ void cp_async16(uint32_t dst, const void* src) {
    asm volatile("cp.async.cg.shared.global [%0], [%1], 16;" :: "r"(dst), "l"(src));
}
__device__ __forceinline__ void cp_commit() {
    asm volatile("cp.async.commit_group;" ::: "memory");
}
template<int N> __device__ __forceinline__ void cp_wait() {
    asm volatile("cp.async.wait_group %0;" :: "n"(N) : "memory");
}
__device__ __forceinline__ void bar_sync(int id, int cnt) {
    asm volatile("bar.sync %0, %1;" :: "r"(id), "r"(cnt) : "memory");
}

#define LDSM_X4(r, addr) \
    asm volatile("ldmatrix.sync.aligned.m8n8.x4.shared.b16 {%0,%1,%2,%3}, [%4];" \
        : "=r"((r)[0]), "=r"((r)[1]), "=r"((r)[2]), "=r"((r)[3]) : "r"(addr))

__device__ __forceinline__ void mma16816(float* c, const uint32_t* a, const uint32_t* b) {
    asm volatile(
        "mma.sync.aligned.m16n8k16.row.col.f32.f16.f16.f32 "
        "{%0,%1,%2,%3}, {%4,%5,%6,%7}, {%8,%9}, {%0,%1,%2,%3};"
        : "+f"(c[0]), "+f"(c[1]), "+f"(c[2]), "+f"(c[3])
        : "r"(a[0]), "r"(a[1]), "r"(a[2]), "r"(a[3]), "r"(b[0]), "r"(b[1]));
}

__device__ __forceinline__ uint32_t pack2h(float v0, float v1) {
    uint32_t r;
    asm("cvt.rn.f16x2.f32 %0, %1, %2;" : "=r"(r) : "f"(v1), "f"(v0));
    return r;
}

// ---------------------------------------------------------------------------
// 1-pass GEMM mainloop: 128x128 tile, BK=32, 3-stage cp.async pipeline.
// ---------------------------------------------------------------------------
#define PITCHB 80
#define AB128 (128 * PITCHB)
#define STAGE1 (2 * AB128)             // 20480
#define SMEM_PROJ (3 * STAGE1)         // 61440

__device__ __forceinline__ void mma_mainloop128_1p(
    uint32_t sb, float (&acc)[2][8][4],
    const fp16* __restrict__ Ahi, int lda, int arow0,
    const fp16* __restrict__ Bhi, int ldb, int brow0,
    int nchunks)
{
    const int tid = threadIdx.x, lane = tid & 31, wid = tid >> 5;
    const int wm = (wid & 3) * 32, wn = (wid >> 2) * 64;

    auto load = [&](int c) {
        uint32_t s = sb + (uint32_t)(c % 3) * STAGE1;
        const int k0 = c * 32;
        for (int i = tid; i < 128 * 4; i += 256) {
            int r = i >> 2, cb = (i & 3) << 4;
            cp_async16(s + (uint32_t)(r * PITCHB + cb),
                       (const char*)(Ahi + (size_t)(arow0 + r) * lda + k0) + cb);
            cp_async16(s + AB128 + (uint32_t)(r * PITCHB + cb),
                       (const char*)(Bhi + (size_t)(brow0 + r) * ldb + k0) + cb);
        }
        cp_commit();
    };

    const uint32_t aoff = (uint32_t)((wm + (lane & 15)) * PITCHB + ((lane & 16) ? 16 : 0));
    const uint32_t boff = (uint32_t)((wn + (lane & 7) + ((lane & 16) ? 8 : 0)) * PITCHB +
                                     ((lane & 8) ? 16 : 0));

    load(0);
    if (nchunks > 1) load(1);
    for (int c = 0; c < nchunks; c++) {
        if (c + 2 < nchunks) { load(c + 2); cp_wait<2>(); }
        else if (c + 1 < nchunks) cp_wait<1>();
        else cp_wait<0>();
        __syncthreads();
        uint32_t s  = sb + (uint32_t)(c % 3) * STAGE1;
        uint32_t sa = s + aoff;
        uint32_t sbb = s + AB128 + boff;
#pragma unroll
        for (int ks = 0; ks < 2; ks++) {
            const uint32_t ko = (uint32_t)(ks * 32);
            uint32_t ah[2][4];
            LDSM_X4(ah[0], sa + ko);
            LDSM_X4(ah[1], sa + 16 * PITCHB + ko);
            uint32_t bh[8][2];
#pragma unroll
            for (int p = 0; p < 4; p++) {
                uint32_t r4[4];
                LDSM_X4(r4, sbb + (uint32_t)(p * 16 * PITCHB) + ko);
                bh[2*p][0] = r4[0]; bh[2*p][1] = r4[1];
                bh[2*p+1][0] = r4[2]; bh[2*p+1][1] = r4[3];
            }
#pragma unroll
            for (int f = 0; f < 2; f++)
#pragma unroll
                for (int j = 0; j < 8; j++)
                    mma16816(acc[f][j], ah[f], bh[j]);
        }
        __syncthreads();
    }
}

// ---------------------------------------------------------------------------
// Merged Q/K/V projections: grid(8, 16, 3). z: 0=Q (scale 0.125), 1=K, 2=V(T).
// ---------------------------------------------------------------------------
__global__ __launch_bounds__(256, 2) void gemm_qkv(
    const float* __restrict__ bq, const float* __restrict__ bk, const float* __restrict__ bv)
{
    extern __shared__ char smem[];
    uint32_t sb = smem_u32(smem);
    const int z = blockIdx.z;
    const int row0 = blockIdx.y << 7, col0 = blockIdx.x << 7;

    const fp16* Ah = (z == 0) ? g_iq : (z == 1) ? g_ik : g_iv;
    const fp16* Bh = (z == 0) ? g_wq : (z == 1) ? g_wk : g_wv;
    const float* bias = (z == 0) ? bq : (z == 1) ? bk : bv;
    const float scale = (z == 0) ? 0.125f : 1.0f;

    float acc[2][8][4];
#pragma unroll
    for (int f = 0; f < 2; f++)
#pragma unroll
        for (int j = 0; j < 8; j++)
#pragma unroll
            for (int q = 0; q < 4; q++) acc[f][j][q] = 0.f;

    mma_mainloop128_1p(sb, acc, Ah, D_MODEL, row0, Bh, D_MODEL, col0, D_MODEL / 32);

    const int lane = threadIdx.x & 31, wid = threadIdx.x >> 5;
    const int wm = (wid & 3) * 32, wn = (wid >> 2) * 64;
    const int rb = row0 + wm + (lane >> 2);
    const int cb = col0 + wn + (lane & 3) * 2;
    fp16* ohi = (z == 0) ? g_qh : g_kh;
#pragma unroll
    for (int f = 0; f < 2; f++)
#pragma unroll
        for (int j = 0; j < 8; j++)
#pragma unroll
            for (int rh = 0; rh < 2; rh++) {
                const int r = rb + f * 16 + rh * 8;
                const int col = cb + j * 8;
                float v0 = (acc[f][j][rh * 2 + 0] + bias[col])     * scale;
                float v1 = (acc[f][j][rh * 2 + 1] + bias[col + 1]) * scale;
                uint32_t hp = pack2h(v0, v1);
                if (z < 2) {
                    *(uint32_t*)(ohi + (size_t)r * D_MODEL + col) = hp;
                } else {
                    g_vt[(size_t)col * S_LEN + r]       = __ushort_as_half((unsigned short)(hp & 0xffff));
                    g_vt[(size_t)(col + 1) * S_LEN + r] = __ushort_as_half((unsigned short)(hp >> 16));
                }
            }
}

// ---------------------------------------------------------------------------
// Output projection: Out = Zhi * Wo_hi^T + badj  (fp32 out)
// ---------------------------------------------------------------------------
__global__ __launch_bounds__(256, 2) void gemm_out(float* __restrict__ ofp)
{
    extern __shared__ char smem[];
    uint32_t sb = smem_u32(smem);
    const int row0 = blockIdx.y << 7, col0 = blockIdx.x << 7;
    float acc[2][8][4];
#pragma unroll
    for (int f = 0; f < 2; f++)
#pragma unroll
        for (int j = 0; j < 8; j++)
#pragma unroll
            for (int q = 0; q < 4; q++) acc[f][j][q] = 0.f;

    mma_mainloop128_1p(sb, acc, g_zh, D_MODEL, row0, g_wo, D_MODEL, col0, D_MODEL / 32);

    const int lane = threadIdx.x & 31, wid = threadIdx.x >> 5;
    const int wm = (wid & 3) * 32, wn = (wid >> 2) * 64;
    const int rb = row0 + wm + (lane >> 2);
    const int cb = col0 + wn + (lane & 3) * 2;
#pragma unroll
    for (int f = 0; f < 2; f++)
#pragma unroll
        for (int j = 0; j < 8; j++)
#pragma unroll
            for (int rh = 0; rh < 2; rh++) {
                const int r = rb + f * 16 + rh * 8;
                const int col = cb + j * 8;
                *(float2*)(ofp + (size_t)r * D_MODEL + col) = make_float2(
                    acc[f][j][rh * 2 + 0] + g_badj[col],
                    acc[f][j][rh * 2 + 1] + g_badj[col + 1]);
            }
}

// ---------------------------------------------------------------------------
// Fused attention, 512 threads = 2 independent warp-groups per CTA.
// Group 0 -> s-block bx, group 1 -> s-block 15-bx (balanced pairing),
// running CONCURRENTLY with separate smem pipelines + named barriers.
// ---------------------------------------------------------------------------
#define PQB  144
#define PVB  272
#define QSZ  (128 * PQB)              // 18432
#define VSZ  (64 * PVB)               // 17408
#define OFF_K    QSZ                              // 18432 (K hi, 2 stages)
#define OFF_V    (OFF_K + 2 * QSZ)                // 55296 (V hi, 2 stages)
#define OFF_PART (OFF_V + 2 * VSZ)                // 90112
#define FHALF    (OFF_PART + 8 * 128 * 4)         // 94208 per warp-group
#define FATTN_SMEM (2 * FHALF)                    // 188416

__global__ __launch_bounds__(512) void fused_attn()
{
    extern __shared__ char smem[];
    const int tid512 = threadIdx.x;
    const int wg   = tid512 >> 8;          // warp-group 0/1
    const int tid  = tid512 & 255;         // id within group
    const int lane = tid & 31, wid = tid >> 5;
    const int h = blockIdx.y;
    const int barid = wg + 1;

    uint32_t sb = smem_u32(smem) + (uint32_t)wg * FHALF;
    float* spart = (float*)(smem + wg * FHALF + OFF_PART);

    const int sblk = wg ? (15 - (int)blockIdx.x) : (int)blockIdx.x;
    const int row0 = sblk << 7;
    const int ntb  = sblk + 1;

    const uint32_t qoff = sb + (uint32_t)((wid * 16 + (lane & 15)) * PQB + ((lane & 16) ? 16 : 0));
    const uint32_t kvlane = (uint32_t)((lane & 7) + ((lane & 16) ? 8 : 0));
    const uint32_t koff_l = kvlane * PQB + ((lane & 8) ? 16 : 0);
    const uint32_t voff_l = kvlane * PVB + ((lane & 8) ? 16 : 0);

    // Q tile (hi only)
    for (int i = tid; i < 128 * 8; i += 256) {
        int r = i >> 3, cbyte = (i & 7) << 4;
        cp_async16(sb + (uint32_t)(r * PQB) + cbyte,
                   (const char*)(g_qh + (size_t)(row0 + r) * D_MODEL + h * HDIM) + cbyte);
    }
    cp_commit();

    auto loadKV = [&](int tb) {
        uint32_t kbase = sb + OFF_K + (uint32_t)(tb & 1) * QSZ;
        uint32_t vbase = sb + OFF_V + (uint32_t)(tb & 1) * VSZ;
        const int col0 = tb << 7;
        for (int i = tid; i < 128 * 8; i += 256) {
            int r = i >> 3, cbyte = (i & 7) << 4;
            cp_async16(kbase + (uint32_t)(r * PQB) + cbyte,
                       (const char*)(g_kh + (size_t)(col0 + r) * D_MODEL + h * HDIM) + cbyte);
        }
        for (int i = tid; i < 64 * 16; i += 256) {
            int r = i >> 4, cbyte = (i & 15) << 4;
            cp_async16(vbase + (uint32_t)(r * PVB) + cbyte,
                       (const char*)(g_vt + (size_t)(h * HDIM + r) * S_LEN + col0) + cbyte);
        }
        cp_commit();
    };
    loadKV(0);

    float oacc[8][4];
#pragma unroll
    for (int j = 0; j < 8; j++)
#pragma unroll
        for (int q = 0; q < 4; q++) oacc[j][q] = 0.f;

    for (int tb = 0; tb < ntb; tb++) {
        if (tb + 1 < ntb) { loadKV(tb + 1); cp_wait<1>(); }
        else              { cp_wait<0>(); }
        bar_sync(barid, 256);

        uint32_t kbase = sb + OFF_K + (uint32_t)(tb & 1) * QSZ;
        uint32_t vbase = sb + OFF_V + (uint32_t)(tb & 1) * VSZ;

        const bool diag = (tb == sblk);
        const int pmax  = diag ? (wid + 1) : 8;
        const int nfmax = diag ? (2 * wid + 2) : 16;

        // ---- MMA1: S[16 x 128] per warp, 1-pass ----
        float sacc[16][4];
#pragma unroll
        for (int j = 0; j < 16; j++)
#pragma unroll
            for (int q = 0; q < 4; q++) sacc[j][q] = 0.f;

        const uint32_t koff = kbase + koff_l;
#pragma unroll
        for (int ks = 0; ks < 4; ks++) {
            const uint32_t ko = (uint32_t)(ks * 32);
            uint32_t ah[4];
            LDSM_X4(ah, qoff + ko);
#pragma unroll
            for (int p = 0; p < 8; p++) {
                if (p < pmax) {
                    uint32_t bh[4];
                    LDSM_X4(bh, koff + (uint32_t)(p * 16 * PQB) + ko);
                    mma16816(sacc[2*p],   ah, bh);
                    mma16816(sacc[2*p+1], ah, bh + 2);
                }
            }
        }

        // ---- mask + exp partial column sums (MUFU) ----
        const int r0 = row0 + wid * 16 + (lane >> 2);
        const int r1 = r0 + 8;
        const int cb2 = (tb << 7) + 2 * (lane & 3);
#pragma unroll
        for (int nf = 0; nf < 16; nf++) {
            float eA = 0.f, eB = 0.f;
            if (nf < nfmax) {
                const int c0 = cb2 + nf * 8;
                float s0 = sacc[nf][0], s1 = sacc[nf][1];
                float s2 = sacc[nf][2], s3 = sacc[nf][3];
                bool m0 = true, m1 = true, m2 = true, m3 = true;
                if (diag) {
                    m0 = (c0 <= r0); m1 = (c0 + 1 <= r0);
                    m2 = (c0 <= r1); m3 = (c0 + 1 <= r1);
                    s0 = m0 ? s0 : 0.f; s1 = m1 ? s1 : 0.f;
                    s2 = m2 ? s2 : 0.f; s3 = m3 ? s3 : 0.f;
                    sacc[nf][0] = s0; sacc[nf][1] = s1;
                    sacc[nf][2] = s2; sacc[nf][3] = s3;
                }
                float e0 = __expf(s0), e1 = __expf(s1);
                float e2 = __expf(s2), e3 = __expf(s3);
                if (diag) {
                    e0 = m0 ? e0 : 0.f; e1 = m1 ? e1 : 0.f;
                    e2 = m2 ? e2 : 0.f; e3 = m3 ? e3 : 0.f;
                }
                eA = e0 + e2; eB = e1 + e3;
                eA += __shfl_xor_sync(0xffffffffu, eA, 4);
                eA += __shfl_xor_sync(0xffffffffu, eA, 8);
                eA += __shfl_xor_sync(0xffffffffu, eA, 16);
                eB += __shfl_xor_sync(0xffffffffu, eB, 4);
                eB += __shfl_xor_sync(0xffffffffu, eB, 8);
                eB += __shfl_xor_sync(0xffffffffu, eB, 16);
            }
            if (lane < 4) {
                spart[wid * 128 + nf * 8 + 2 * lane]     = eA;
                spart[wid * 128 + nf * 8 + 2 * lane + 1] = eB;
            }
        }

        // ---- MMA2: O += S_hi @ V_hi^T, 1-pass ----
        const uint32_t voff = vbase + voff_l;
#pragma unroll
        for (int kc = 0; kc < 8; kc++) {
            if (kc < pmax) {
                uint32_t ahi[4];
                ahi[0] = pack2h(sacc[2*kc][0],   sacc[2*kc][1]);
                ahi[1] = pack2h(sacc[2*kc][2],   sacc[2*kc][3]);
                ahi[2] = pack2h(sacc[2*kc+1][0], sacc[2*kc+1][1]);
                ahi[3] = pack2h(sacc[2*kc+1][2], sacc[2*kc+1][3]);
                const uint32_t ko = (uint32_t)(kc * 32);
#pragma unroll
                for (int p = 0; p < 4; p++) {
                    uint32_t bh[4];
                    LDSM_X4(bh, voff + (uint32_t)(p * 16 * PVB) + ko);
                    mma16816(oacc[2*p],   ahi, bh);
                    mma16816(oacc[2*p+1], ahi, bh + 2);
                }
            }
        }

        bar_sync(barid, 256);
        if (tid < 128) {
            float s = 0.f;
#pragma unroll
            for (int w = 0; w < 8; w++) s += spart[w * 128 + tid];
            g_part[((h * 16 + sblk) << 11) + (tb << 7) + tid] = s;
        }
    }

    // ---- epilogue: Z_hi = fp16(O) ----
    {
        const int r0 = row0 + wid * 16 + (lane >> 2);
        const int cb2 = 2 * (lane & 3);
#pragma unroll
        for (int nf = 0; nf < 8; nf++) {
            const int col = h * HDIM + nf * 8 + cb2;
            *(uint32_t*)(g_zh + (size_t)r0 * D_MODEL + col)       = pack2h(oacc[nf][0], oacc[nf][1]);
            *(uint32_t*)(g_zh + (size_t)(r0 + 8) * D_MODEL + col) = pack2h(oacc[nf][2], oacc[nf][3]);
        }
    }
}

// ---------------------------------------------------------------------------
// L[h][t] = log( t + sum_{sb>=tb} part[h][sb][t] )
// ---------------------------------------------------------------------------
__global__ __launch_bounds__(128) void lse_reduce()
{
    const int h = blockIdx.y, tb = blockIdx.x;
    const int t = (tb << 7) + threadIdx.x;
    float acc = (float)t;
    for (int sbk = tb; sbk < 16; sbk++)
        acc += g_part[((h * 16 + sbk) << 11) + t];
    g_L[h * S_LEN + t] = logf(acc);
}

// ---------------------------------------------------------------------------
// c[h][v] = sum_t L[h][t] * V[t][h*64+v]   (V hi)
// ---------------------------------------------------------------------------
__global__ __launch_bounds__(256) void compute_c_tc()
{
    __shared__ float part[4][HDIM];
    const int h = blockIdx.x;
    const int v = threadIdx.x & 63;
    const int g = threadIdx.x >> 6;
    const fp16* th = g_vt + (size_t)(h * HDIM + v) * S_LEN;
    const float* Lh = g_L + h * S_LEN;
    float sum = 0.f;
    const int t0 = g * (S_LEN / 4);
    for (int t = t0; t < t0 + S_LEN / 4; t++)
        sum = fmaf(Lh[t], __half2float(th[t]), sum);
    part[g][v] = sum;
    __syncthreads();
    if (g == 0)
        g_c[h * HDIM + v] = (part[0][v] + part[1][v]) + (part[2][v] + part[3][v]);
}

// ---------------------------------------------------------------------------
// b'[i] = WOb[i] - sum_j WOw[i][j] * c[j]
// ---------------------------------------------------------------------------
__global__ __launch_bounds__(256) void bias_adjust(
    const float* __restrict__ WOw, const float* __restrict__ WOb)
{
    const int lane = threadIdx.x & 31, wid = threadIdx.x >> 5;
    for (int rr = 0; rr < 4; rr++) {
        const int row = (blockIdx.x * 8 + wid) * 4 + rr;
        const float* wr = WOw + (size_t)row * D_MODEL;
        float s = 0.f;
        for (int j = lane; j < D_MODEL; j += 32)
            s = fmaf(wr[j], g_c[j], s);
#pragma unroll
        for (int o = 16; o > 0; o >>= 1) s += __shfl_xor_sync(0xffffffffu, s, o);
        if (lane == 0) g_badj[row] = WOb[row] - s;
    }
}

// ---------------------------------------------------------------------------
// One-shot fp32 -> fp16 conversion: 3 inputs + 4 weights, hi only.
// ---------------------------------------------------------------------------
__global__ __launch_bounds__(256) void split_all(
    const float4* __restrict__ Qin, const float4* __restrict__ Kin, const float4* __restrict__ Vin,
    const float4* __restrict__ WQw, const float4* __restrict__ WKw,
    const float4* __restrict__ WVw, const float4* __restrict__ WOw)
{
    const int b = blockIdx.x;
    const float4* src;
    uint4* hi;
    int rb;
    if (b < 3072) {
        const int t = b >> 10; rb = b & 1023;
        src = (t == 0) ? Qin : (t == 1) ? Kin : Vin;
        hi = (uint4*)((t == 0) ? g_iq : (t == 1) ? g_ik : g_iv);
    } else {
        const int bb = b - 3072, t = bb >> 9; rb = bb & 511;
        src = (t == 0) ? WQw : (t == 1) ? WKw : (t == 2) ? WVw : WOw;
        hi = (uint4*)((t == 0) ? g_wq : (t == 1) ? g_wk : (t == 2) ? g_wv : g_wo);
    }
    const int i = rb * 256 + threadIdx.x;
    float4 a = src[2 * i], c = src[2 * i + 1];
    hi[i] = make_uint4(pack2h(a.x, a.y), pack2h(a.z, a.w),
                       pack2h(c.x, c.y), pack2h(c.z, c.w));
}

// ---------------------------------------------------------------------------
extern "C" void kernel_launch(void* const* d_in, const int* in_sizes, int n_in,
                              void* d_out, int out_size)
{
    const float* Qin = (const float*)d_in[0];
    const float* Kin = (const float*)d_in[1];
    const float* Vin = (const float*)d_in[2];
    const float* WQw = (const float*)d_in[3];
    const float* WQb = (const float*)d_in[4];
    const float* WKw = (const float*)d_in[5];
    const float* WKb = (const float*)d_in[6];
    const float* WVw = (const float*)d_in[7];
    const float* WVb = (const float*)d_in[8];
    const float* WOw = (const float*)d_in[9];
    const float* WOb = (const float*)d_in[10];
    float* Out = (float*)d_out;

    cudaFuncSetAttribute(gemm_qkv,   cudaFuncAttributeMaxDynamicSharedMemorySize, SMEM_PROJ);
    cudaFuncSetAttribute(gemm_out,   cudaFuncAttributeMaxDynamicSharedMemorySize, SMEM_PROJ);
    cudaFuncSetAttribute(fused_attn, cudaFuncAttributeMaxDynamicSharedMemorySize, FATTN_SMEM);

    dim3 blk(256);

    // 1) fp16 conversions
    split_all<<<5120, blk>>>((const float4*)Qin, (const float4*)Kin, (const float4*)Vin,
                             (const float4*)WQw, (const float4*)WKw,
                             (const float4*)WVw, (const float4*)WOw);

    // 2) Q/K/V projections
    dim3 gqkv(D_MODEL / 128, S_LEN / 128, 3);
    gemm_qkv<<<gqkv, blk, SMEM_PROJ>>>(WQb, WKb, WVb);

    // 3) fused attention (512 threads, 2 concurrent warp-groups)
    dim3 gfa(8, NHEAD);
    fused_attn<<<gfa, dim3(512), FATTN_SMEM>>>();

    // 4) L, c, adjusted bias
    dim3 glse(16, NHEAD);
    lse_reduce<<<glse, dim3(128)>>>();
    compute_c_tc<<<NHEAD, blk>>>();
    bias_adjust<<<32, blk>>>(WOw, WOb);

    // 5) output projection with folded bias
    dim3 gout(D_MODEL / 128, S_LEN / 128);
    gemm_out<<<gout, blk, SMEM_PROJ>>>(Out);
}